// round 1
// baseline (speedup 1.0000x reference)
#include <cuda_runtime.h>
#include <cstdint>

// Problem constants (fixed by the reference)
#define S_TOT  16384
#define HID    1280
#define NH     16
#define HD     80
#define WIN    64
#define NW     256          // 16384 / 64
#define QKV_N  3840         // 3 * HID
#define ROT    40           // HEAD_DIM / 2

// ---------------------------------------------------------------------------
// Scratch (device globals: allocation-guard-safe)
// ---------------------------------------------------------------------------
__device__ float g_qkv [(size_t)S_TOT * QKV_N];   // [S, 3, H, D] fp32 (252 MB)
__device__ float g_attn[(size_t)S_TOT * HID];     // [S, H*D]     fp32 (84 MB)

// ---------------------------------------------------------------------------
// GEMM: C[M,N] = A[M,K] * B[N,K]^T + bias[N]
// A row-major [M,K], B row-major [N,K] (both K-major -> coalesced loads).
// 128x128 tile, BK=8, 256 threads, 8x8 per thread. Requires M%128==0, N%128==0,
// K%8==0 (holds for all shapes here).
// ---------------------------------------------------------------------------
__global__ void __launch_bounds__(256)
gemm_bias_kernel(const float* __restrict__ A, const float* __restrict__ B,
                 const float* __restrict__ bias, float* __restrict__ C,
                 int M, int N, int K)
{
    const int BM = 128, BN = 128, BK = 8;
    __shared__ float As[BK][BM];
    __shared__ float Bs[BK][BN];

    const int tid = threadIdx.x;
    const int bm  = blockIdx.y * BM;
    const int bn  = blockIdx.x * BN;
    const int tx  = tid & 15;       // 0..15  (col group)
    const int ty  = tid >> 4;       // 0..15  (row group)

    float acc[8][8];
    #pragma unroll
    for (int i = 0; i < 8; i++)
        #pragma unroll
        for (int j = 0; j < 8; j++) acc[i][j] = 0.f;

    const int ld_row = tid >> 1;          // 0..127
    const int ld_col = (tid & 1) * 4;     // 0 or 4
    const float* Aptr = A + (size_t)(bm + ld_row) * K + ld_col;
    const float* Bptr = B + (size_t)(bn + ld_row) * K + ld_col;

    for (int k0 = 0; k0 < K; k0 += BK) {
        float4 av = *(const float4*)(Aptr + k0);
        float4 bv = *(const float4*)(Bptr + k0);
        As[ld_col + 0][ld_row] = av.x;
        As[ld_col + 1][ld_row] = av.y;
        As[ld_col + 2][ld_row] = av.z;
        As[ld_col + 3][ld_row] = av.w;
        Bs[ld_col + 0][ld_row] = bv.x;
        Bs[ld_col + 1][ld_row] = bv.y;
        Bs[ld_col + 2][ld_row] = bv.z;
        Bs[ld_col + 3][ld_row] = bv.w;
        __syncthreads();

        #pragma unroll
        for (int k = 0; k < BK; k++) {
            float4 a0 = *(const float4*)&As[k][ty * 8];
            float4 a1 = *(const float4*)&As[k][ty * 8 + 4];
            float4 b0 = *(const float4*)&Bs[k][tx * 8];
            float4 b1 = *(const float4*)&Bs[k][tx * 8 + 4];
            float ar[8] = {a0.x, a0.y, a0.z, a0.w, a1.x, a1.y, a1.z, a1.w};
            float br[8] = {b0.x, b0.y, b0.z, b0.w, b1.x, b1.y, b1.z, b1.w};
            #pragma unroll
            for (int i = 0; i < 8; i++)
                #pragma unroll
                for (int j = 0; j < 8; j++)
                    acc[i][j] += ar[i] * br[j];
        }
        __syncthreads();
    }

    #pragma unroll
    for (int i = 0; i < 8; i++) {
        const int row = bm + ty * 8 + i;
        #pragma unroll
        for (int j = 0; j < 8; j += 4) {
            const int col = bn + tx * 8 + j;
            float4 o;
            o.x = acc[i][j + 0] + bias[col + 0];
            o.y = acc[i][j + 1] + bias[col + 1];
            o.z = acc[i][j + 2] + bias[col + 2];
            o.w = acc[i][j + 3] + bias[col + 3];
            *(float4*)&C[(size_t)row * N + col] = o;
        }
    }
}

// ---------------------------------------------------------------------------
// RoPE, in place on q (channel 0) and k (channel 1) of g_qkv.
// One thread per (s, h, j) with j in [0, 40).
// ---------------------------------------------------------------------------
__global__ void rope_kernel(float* __restrict__ qkv,
                            const float* __restrict__ cosT,
                            const float* __restrict__ sinT)
{
    const int total = S_TOT * NH * ROT;
    int idx = blockIdx.x * blockDim.x + threadIdx.x;
    if (idx >= total) return;

    const int j = idx % ROT;
    const int h = (idx / ROT) % NH;
    const int s = idx / (ROT * NH);

    const float c  = cosT[s * ROT + j];
    const float sn = sinT[s * ROT + j];

    size_t base = (size_t)s * QKV_N + h * HD;     // q
    float q1 = qkv[base + j], q2 = qkv[base + ROT + j];
    qkv[base + j]       = q1 * c - q2 * sn;
    qkv[base + ROT + j] = q2 * c + q1 * sn;

    base += HID;                                   // k
    float k1 = qkv[base + j], k2 = qkv[base + ROT + j];
    qkv[base + j]       = k1 * c - k2 * sn;
    qkv[base + ROT + j] = k2 * c + k1 * sn;
}

// ---------------------------------------------------------------------------
// Windowed attention: one block per (window, head). 256 threads.
// smem: q[64*81] + k[64*81] + v[64*80] + scores[64*64]  = 78336 bytes.
// stride 81 (17 mod 32, coprime with 32) -> conflict-free K-row reads.
// ---------------------------------------------------------------------------
__global__ void __launch_bounds__(256)
attn_kernel(const float* __restrict__ qkv, float* __restrict__ outp)
{
    extern __shared__ float sm[];
    float* qs = sm;                     // 64*81
    float* ks = sm + WIN * 81;          // 64*81
    float* vs = ks + WIN * 81;          // 64*80
    float* sc = vs + WIN * HD;          // 64*64

    const int tid = threadIdx.x;
    const int w   = blockIdx.x >> 4;    // window index
    const int h   = blockIdx.x & 15;    // head index
    const int s0  = w * WIN;

    for (int i = tid; i < WIN * HD; i += 256) {
        const int r = i / HD, d = i % HD;
        const size_t rb = (size_t)(s0 + r) * QKV_N + h * HD + d;
        qs[r * 81 + d] = qkv[rb];
        ks[r * 81 + d] = qkv[rb + HID];
        vs[r * HD + d] = qkv[rb + 2 * HID];
    }
    __syncthreads();

    const float scale = 0.11180339887498949f;   // 1/sqrt(80)
    for (int idx = tid; idx < WIN * WIN; idx += 256) {
        const int qi = idx >> 6, kj = idx & 63;
        float sum = 0.f;
        #pragma unroll 8
        for (int d = 0; d < HD; d++)
            sum += qs[qi * 81 + d] * ks[kj * 81 + d];
        sc[idx] = sum * scale;
    }
    __syncthreads();

    if (tid < WIN) {
        float m = -1e30f;
        #pragma unroll 4
        for (int j = 0; j < WIN; j++) m = fmaxf(m, sc[tid * WIN + j]);
        float ssum = 0.f;
        #pragma unroll 4
        for (int j = 0; j < WIN; j++) {
            float e = __expf(sc[tid * WIN + j] - m);
            sc[tid * WIN + j] = e;
            ssum += e;
        }
        const float inv = 1.f / ssum;
        #pragma unroll 4
        for (int j = 0; j < WIN; j++) sc[tid * WIN + j] *= inv;
    }
    __syncthreads();

    for (int idx = tid; idx < WIN * HD; idx += 256) {
        const int qi = idx / HD, d = idx % HD;
        float sum = 0.f;
        #pragma unroll 8
        for (int kj = 0; kj < WIN; kj++)
            sum += sc[qi * WIN + kj] * vs[kj * HD + d];
        outp[(size_t)(s0 + qi) * HID + h * HD + d] = sum;
    }
}

// ---------------------------------------------------------------------------
// Launch
// ---------------------------------------------------------------------------
extern "C" void kernel_launch(void* const* d_in, const int* in_sizes, int n_in,
                              void* d_out, int out_size)
{
    const float* x      = (const float*)d_in[0];
    const float* cosT   = (const float*)d_in[1];
    const float* sinT   = (const float*)d_in[2];
    const float* qkv_w  = (const float*)d_in[3];
    const float* qkv_b  = (const float*)d_in[4];
    const float* proj_w = (const float*)d_in[5];
    const float* proj_b = (const float*)d_in[6];
    float* out = (float*)d_out;

    float* qkv = nullptr;
    float* attn = nullptr;
    cudaGetSymbolAddress((void**)&qkv,  g_qkv);
    cudaGetSymbolAddress((void**)&attn, g_attn);

    // attention smem opt-in (78336 B > 48 KB default)
    const int attn_smem = (WIN * 81 * 2 + WIN * HD + WIN * WIN) * (int)sizeof(float);
    cudaFuncSetAttribute(attn_kernel, cudaFuncAttributeMaxDynamicSharedMemorySize,
                         attn_smem);

    // 1) QKV GEMM + bias  -> g_qkv
    {
        dim3 grid(QKV_N / 128, S_TOT / 128);   // (30, 128)
        gemm_bias_kernel<<<grid, 256>>>(x, qkv_w, qkv_b, qkv, S_TOT, QKV_N, HID);
    }
    // 2) RoPE in-place on q, k
    {
        const int total = S_TOT * NH * ROT;
        rope_kernel<<<(total + 255) / 256, 256>>>(qkv, cosT, sinT);
    }
    // 3) windowed attention -> g_attn
    {
        attn_kernel<<<NW * NH, 256, attn_smem>>>(qkv, attn);
    }
    // 4) output projection + bias -> d_out
    {
        dim3 grid(HID / 128, S_TOT / 128);     // (10, 128)
        gemm_bias_kernel<<<grid, 256>>>(attn, proj_w, proj_b, out, S_TOT, HID, HID);
    }
}

// round 4
// speedup vs baseline: 2.4115x; 2.4115x over previous
#include <cuda_runtime.h>
#include <cstdint>

// Problem constants
#define S_TOT  16384
#define HID    1280
#define NH     16
#define HD     80
#define WIN    64
#define NW     256
#define QKV_N  3840
#define ROT    40

// mma.sync tf32 GEMM tiling
#define BM 128
#define BN 128
#define BK 32
#define NS 4                        // cp.async pipeline stages
#define ASTRIDE 40                  // smem row stride in floats (bank-pair clean)
#define TILE_BYTES (128 * ASTRIDE * 4)          // one 128-row matrix per stage
#define STAGE_BYTES (2 * TILE_BYTES)            // A + B
#define GEMM_SMEM (NS * STAGE_BYTES)            // 163840 B

// ---------------------------------------------------------------------------
// Scratch (device globals: allocation-guard-safe)
// ---------------------------------------------------------------------------
__device__ float g_qkv [(size_t)S_TOT * QKV_N];   // 252 MB
__device__ float g_attn[(size_t)S_TOT * HID];     // 84 MB

// ---------------------------------------------------------------------------
// PTX helpers (sm_100 base target: cp.async + mma.sync only)
// ---------------------------------------------------------------------------
__device__ __forceinline__ uint32_t smem_u32(const void* p) {
    uint32_t a;
    asm("{ .reg .u64 t; cvta.to.shared.u64 t, %1; cvt.u32.u64 %0, t; }"
        : "=r"(a) : "l"(p));
    return a;
}
__device__ __forceinline__ void cp16(uint32_t dst, const void* src) {
    asm volatile("cp.async.cg.shared.global [%0], [%1], 16;" :: "r"(dst), "l"(src));
}
#define CP_COMMIT()  asm volatile("cp.async.commit_group;" ::: "memory")
#define CP_WAIT(n)   asm volatile("cp.async.wait_group %0;" :: "n"(n) : "memory")

// ld.shared.v2.f32 + round-to-nearest tf32 conversion
__device__ __forceinline__ void lds_tf32x2(uint32_t& r0, uint32_t& r1, uint32_t addr) {
    float f0, f1;
    asm volatile("ld.shared.v2.f32 {%0,%1}, [%2];" : "=f"(f0), "=f"(f1) : "r"(addr));
    asm("cvt.rna.tf32.f32 %0, %1;" : "=r"(r0) : "f"(f0));
    asm("cvt.rna.tf32.f32 %0, %1;" : "=r"(r1) : "f"(f1));
}

__device__ __forceinline__ void mma_tf32(float* c, const uint32_t* a, const uint32_t* b) {
    asm volatile(
        "mma.sync.aligned.m16n8k8.row.col.f32.tf32.tf32.f32 "
        "{%0,%1,%2,%3}, {%4,%5,%6,%7}, {%8,%9}, {%0,%1,%2,%3};"
        : "+f"(c[0]), "+f"(c[1]), "+f"(c[2]), "+f"(c[3])
        : "r"(a[0]), "r"(a[1]), "r"(a[2]), "r"(a[3]), "r"(b[0]), "r"(b[1]));
}

// ---------------------------------------------------------------------------
// tf32 mma.sync GEMM: C[M,N] = A[M,K] * B[N,K]^T + bias[N]
// Both operands K-major fp32. 256 threads, 8 warps (2 M x 4 N), warp tile 64x32.
// K-permutation: logical col c<4 -> phys 2c ; c>=4 -> phys 2(c-4)+1, applied
// identically to A and B (sum over K is order-invariant) so every fragment
// load is one lds.64.
// Requires M%128==0, N%128==0, K%32==0.
// ---------------------------------------------------------------------------
__device__ __forceinline__ void load_stage(uint32_t stage_base,
                                           const float* __restrict__ A,
                                           const float* __restrict__ B,
                                           int bm, int bn, int K, int k0, int tid)
{
    const int row = tid >> 3;            // 0..31 step: 4 iters cover 128 rows
    const int c4  = tid & 7;             // 0..7  (float4 column)
    const float* Ap = A + (size_t)(bm + row) * K + k0 + c4 * 4;
    const float* Bp = B + (size_t)(bn + row) * K + k0 + c4 * 4;
    uint32_t dstA = stage_base + (row * ASTRIDE + c4 * 4) * 4;
    uint32_t dstB = dstA + TILE_BYTES;
    #pragma unroll
    for (int i = 0; i < 4; i++) {
        cp16(dstA + i * 32 * ASTRIDE * 4, Ap + (size_t)(i * 32) * K);
        cp16(dstB + i * 32 * ASTRIDE * 4, Bp + (size_t)(i * 32) * K);
    }
}

__global__ void __launch_bounds__(256)
gemm_tc_kernel(const float* __restrict__ A, const float* __restrict__ B,
               const float* __restrict__ bias, float* __restrict__ C,
               int M, int N, int K)
{
    extern __shared__ char smraw[];
    const uint32_t smem_base = smem_u32(smraw);
    const int tid  = threadIdx.x;
    const int wid  = tid >> 5;
    const int lane = tid & 31;
    const int g    = lane >> 2;          // 0..7
    const int t    = lane & 3;           // 0..3
    const int wm   = wid >> 2;           // 0..1  (M warp)
    const int wn   = wid & 3;            // 0..3  (N warp)
    const int bm   = blockIdx.y * BM;
    const int bn   = blockIdx.x * BN;

    float acc[4][4][4];
    #pragma unroll
    for (int mi = 0; mi < 4; mi++)
        #pragma unroll
        for (int ni = 0; ni < 4; ni++)
            #pragma unroll
            for (int r = 0; r < 4; r++) acc[mi][ni][r] = 0.f;

    const int KT = K / BK;

    // Prologue: fill NS-1 stages
    #pragma unroll
    for (int s = 0; s < NS - 1; s++) {
        load_stage(smem_base + s * STAGE_BYTES, A, B, bm, bn, K, s * BK, tid);
        CP_COMMIT();
    }

    // Per-thread fragment base offsets (bytes) within a stage
    const uint32_t a_base = ((wm * 64 + g) * ASTRIDE + 2 * t) * 4;
    const uint32_t b_base = TILE_BYTES + ((wn * 32 + g) * ASTRIDE + 2 * t) * 4;

    for (int kt = 0; kt < KT; kt++) {
        CP_WAIT(NS - 2);
        __syncthreads();

        if (kt + NS - 1 < KT) {
            load_stage(smem_base + ((kt + NS - 1) & (NS - 1)) * STAGE_BYTES,
                       A, B, bm, bn, K, (kt + NS - 1) * BK, tid);
        }
        CP_COMMIT();

        const uint32_t stage = smem_base + (kt & (NS - 1)) * STAGE_BYTES;

        #pragma unroll
        for (int kk = 0; kk < 4; kk++) {
            const uint32_t koff = kk * 8 * 4;     // 8 floats per k-step
            uint32_t af[4][4];
            uint32_t bf[4][2];
            #pragma unroll
            for (int mi = 0; mi < 4; mi++) {
                const uint32_t ab = stage + a_base + mi * 16 * ASTRIDE * 4 + koff;
                lds_tf32x2(af[mi][0], af[mi][2], ab);
                lds_tf32x2(af[mi][1], af[mi][3], ab + 8 * ASTRIDE * 4);
            }
            #pragma unroll
            for (int ni = 0; ni < 4; ni++) {
                const uint32_t bb = stage + b_base + ni * 8 * ASTRIDE * 4 + koff;
                lds_tf32x2(bf[ni][0], bf[ni][1], bb);
            }
            #pragma unroll
            for (int mi = 0; mi < 4; mi++)
                #pragma unroll
                for (int ni = 0; ni < 4; ni++)
                    mma_tf32(acc[mi][ni], af[mi], bf[ni]);
        }
    }

    // Epilogue: bias add + store (c0,c1 are adjacent columns -> float2)
    #pragma unroll
    for (int mi = 0; mi < 4; mi++) {
        const int row0 = bm + wm * 64 + mi * 16 + g;
        #pragma unroll
        for (int ni = 0; ni < 4; ni++) {
            const int col = bn + wn * 32 + ni * 8 + 2 * t;
            const float2 bb = __ldg((const float2*)&bias[col]);
            float2 o0, o1;
            o0.x = acc[mi][ni][0] + bb.x;
            o0.y = acc[mi][ni][1] + bb.y;
            o1.x = acc[mi][ni][2] + bb.x;
            o1.y = acc[mi][ni][3] + bb.y;
            *(float2*)&C[(size_t)row0 * N + col]       = o0;
            *(float2*)&C[(size_t)(row0 + 8) * N + col] = o1;
        }
    }
}

// ---------------------------------------------------------------------------
// RoPE, in place on q (channel 0) and k (channel 1) of g_qkv.
// ---------------------------------------------------------------------------
__global__ void rope_kernel(float* __restrict__ qkv,
                            const float* __restrict__ cosT,
                            const float* __restrict__ sinT)
{
    const int total = S_TOT * NH * ROT;
    int idx = blockIdx.x * blockDim.x + threadIdx.x;
    if (idx >= total) return;

    const int j = idx % ROT;
    const int h = (idx / ROT) % NH;
    const int s = idx / (ROT * NH);

    const float c  = cosT[s * ROT + j];
    const float sn = sinT[s * ROT + j];

    size_t base = (size_t)s * QKV_N + h * HD;
    float q1 = qkv[base + j], q2 = qkv[base + ROT + j];
    qkv[base + j]       = q1 * c - q2 * sn;
    qkv[base + ROT + j] = q2 * c + q1 * sn;

    base += HID;
    float k1 = qkv[base + j], k2 = qkv[base + ROT + j];
    qkv[base + j]       = k1 * c - k2 * sn;
    qkv[base + ROT + j] = k2 * c + k1 * sn;
}

// ---------------------------------------------------------------------------
// Windowed attention: one block per (window, head). 256 threads.
// ---------------------------------------------------------------------------
__global__ void __launch_bounds__(256)
attn_kernel(const float* __restrict__ qkv, float* __restrict__ outp)
{
    extern __shared__ float smf[];
    float* qs = smf;                    // 64*81
    float* ks = smf + WIN * 81;         // 64*81
    float* vs = ks + WIN * 81;          // 64*80
    float* sc = vs + WIN * HD;          // 64*64

    const int tid = threadIdx.x;
    const int w   = blockIdx.x >> 4;
    const int h   = blockIdx.x & 15;
    const int s0  = w * WIN;

    for (int i = tid; i < WIN * HD; i += 256) {
        const int r = i / HD, d = i % HD;
        const size_t rb = (size_t)(s0 + r) * QKV_N + h * HD + d;
        qs[r * 81 + d] = qkv[rb];
        ks[r * 81 + d] = qkv[rb + HID];
        vs[r * HD + d] = qkv[rb + 2 * HID];
    }
    __syncthreads();

    const float scale = 0.11180339887498949f;
    for (int idx = tid; idx < WIN * WIN; idx += 256) {
        const int qi = idx >> 6, kj = idx & 63;
        float sum = 0.f;
        #pragma unroll 8
        for (int d = 0; d < HD; d++)
            sum += qs[qi * 81 + d] * ks[kj * 81 + d];
        sc[idx] = sum * scale;
    }
    __syncthreads();

    if (tid < WIN) {
        float m = -1e30f;
        #pragma unroll 4
        for (int j = 0; j < WIN; j++) m = fmaxf(m, sc[tid * WIN + j]);
        float ssum = 0.f;
        #pragma unroll 4
        for (int j = 0; j < WIN; j++) {
            float e = __expf(sc[tid * WIN + j] - m);
            sc[tid * WIN + j] = e;
            ssum += e;
        }
        const float inv = 1.f / ssum;
        #pragma unroll 4
        for (int j = 0; j < WIN; j++) sc[tid * WIN + j] *= inv;
    }
    __syncthreads();

    for (int idx = tid; idx < WIN * HD; idx += 256) {
        const int qi = idx / HD, d = idx % HD;
        float sum = 0.f;
        #pragma unroll 8
        for (int kj = 0; kj < WIN; kj++)
            sum += sc[qi * WIN + kj] * vs[kj * HD + d];
        outp[(size_t)(s0 + qi) * HID + h * HD + d] = sum;
    }
}

// ---------------------------------------------------------------------------
// Launch
// ---------------------------------------------------------------------------
extern "C" void kernel_launch(void* const* d_in, const int* in_sizes, int n_in,
                              void* d_out, int out_size)
{
    const float* x      = (const float*)d_in[0];
    const float* cosT   = (const float*)d_in[1];
    const float* sinT   = (const float*)d_in[2];
    const float* qkv_w  = (const float*)d_in[3];
    const float* qkv_b  = (const float*)d_in[4];
    const float* proj_w = (const float*)d_in[5];
    const float* proj_b = (const float*)d_in[6];
    float* out = (float*)d_out;

    float* qkv = nullptr;
    float* attn = nullptr;
    cudaGetSymbolAddress((void**)&qkv,  g_qkv);
    cudaGetSymbolAddress((void**)&attn, g_attn);

    const int attn_smem = (WIN * 81 * 2 + WIN * HD + WIN * WIN) * (int)sizeof(float);
    cudaFuncSetAttribute(attn_kernel, cudaFuncAttributeMaxDynamicSharedMemorySize,
                         attn_smem);
    cudaFuncSetAttribute(gemm_tc_kernel, cudaFuncAttributeMaxDynamicSharedMemorySize,
                         GEMM_SMEM);

    // 1) QKV GEMM + bias -> g_qkv   (tf32 mma.sync)
    {
        dim3 grid(QKV_N / BN, S_TOT / BM);   // (30, 128)
        gemm_tc_kernel<<<grid, 256, GEMM_SMEM>>>(x, qkv_w, qkv_b, qkv,
                                                 S_TOT, QKV_N, HID);
    }
    // 2) RoPE in-place on q, k
    {
        const int total = S_TOT * NH * ROT;
        rope_kernel<<<(total + 255) / 256, 256>>>(qkv, cosT, sinT);
    }
    // 3) windowed attention -> g_attn
    {
        attn_kernel<<<NW * NH, 256, attn_smem>>>(qkv, attn);
    }
    // 4) output projection + bias -> d_out   (tf32 mma.sync)
    {
        dim3 grid(HID / BN, S_TOT / BM);     // (10, 128)
        gemm_tc_kernel<<<grid, 256, GEMM_SMEM>>>(attn, proj_w, proj_b, out,
                                                 S_TOT, HID, HID);
    }
}

// round 6
// speedup vs baseline: 3.4977x; 1.4504x over previous
#include <cuda_runtime.h>
#include <cstdint>

// Problem constants
#define S_TOT  16384
#define HID    1280
#define NH     16
#define HD     80
#define WIN    64
#define NW     256
#define QKV_N  3840
#define ROT    40

// mma.sync tf32 GEMM tiling: CTA 128x256, warp tile 64x64, BK=32, 3 stages
#define BM 128
#define BN 256
#define BK 32
#define NS 3
#define ASTRIDE 40                                 // smem row stride (floats)
#define TILE_A_BYTES (128 * ASTRIDE * 4)           // 20480
#define TILE_B_BYTES (256 * ASTRIDE * 4)           // 40960
#define STAGE_BYTES  (TILE_A_BYTES + TILE_B_BYTES) // 61440
#define GEMM_SMEM    (NS * STAGE_BYTES)            // 184320 B

// ---------------------------------------------------------------------------
// Scratch (device globals: allocation-guard-safe)
// ---------------------------------------------------------------------------
__device__ float g_qkv [(size_t)S_TOT * QKV_N];    // 252 MB
__device__ float g_attn[(size_t)S_TOT * HID];      // 84 MB (tf32-rounded)
__device__ float g_xr  [(size_t)S_TOT * HID];      // 84 MB (x, tf32-rounded)
__device__ float g_wr  [(size_t)QKV_N * HID];      // 19.7 MB
__device__ float g_pwr [(size_t)HID * HID];        // 6.6 MB

// ---------------------------------------------------------------------------
// PTX helpers (sm_100 base target)
// ---------------------------------------------------------------------------
__device__ __forceinline__ uint32_t smem_u32(const void* p) {
    uint32_t a;
    asm("{ .reg .u64 t; cvta.to.shared.u64 t, %1; cvt.u32.u64 %0, t; }"
        : "=r"(a) : "l"(p));
    return a;
}
__device__ __forceinline__ void cp16(uint32_t dst, const void* src) {
    asm volatile("cp.async.cg.shared.global [%0], [%1], 16;" :: "r"(dst), "l"(src));
}
#define CP_COMMIT()  asm volatile("cp.async.commit_group;" ::: "memory")
#define CP_WAIT(n)   asm volatile("cp.async.wait_group %0;" :: "n"(n) : "memory")

__device__ __forceinline__ void lds64(uint32_t& r0, uint32_t& r1, uint32_t addr) {
    asm volatile("ld.shared.v2.b32 {%0,%1}, [%2];" : "=r"(r0), "=r"(r1) : "r"(addr));
}
__device__ __forceinline__ float tf32r(float f) {
    uint32_t r;
    asm("cvt.rna.tf32.f32 %0, %1;" : "=r"(r) : "f"(f));
    return __uint_as_float(r);
}
__device__ __forceinline__ void mma_tf32(float* c, const uint32_t* a, const uint32_t* b) {
    asm volatile(
        "mma.sync.aligned.m16n8k8.row.col.f32.tf32.tf32.f32 "
        "{%0,%1,%2,%3}, {%4,%5,%6,%7}, {%8,%9}, {%0,%1,%2,%3};"
        : "+f"(c[0]), "+f"(c[1]), "+f"(c[2]), "+f"(c[3])
        : "r"(a[0]), "r"(a[1]), "r"(a[2]), "r"(a[3]), "r"(b[0]), "r"(b[1]));
}

// ---------------------------------------------------------------------------
// Pre-round fp32 -> tf32-exact fp32 (elementwise, float4)
// ---------------------------------------------------------------------------
__global__ void __launch_bounds__(256)
preround_kernel(const float4* __restrict__ src, float4* __restrict__ dst, int n4)
{
    int i = blockIdx.x * blockDim.x + threadIdx.x;
    if (i < n4) {
        float4 v = src[i];
        v.x = tf32r(v.x); v.y = tf32r(v.y);
        v.z = tf32r(v.z); v.w = tf32r(v.w);
        dst[i] = v;
    }
}

// ---------------------------------------------------------------------------
// tf32 mma.sync GEMM: C[M,N] = A[M,K]*B[N,K]^T + bias[N]
// Inputs MUST already be tf32-exact (pre-rounded): HW truncation is lossless.
// 256 threads, 8 warps (2M x 4N), warp tile 64x64.
// K-permutation: logical col c<4 -> phys 2c; c>=4 -> phys 2(c-4)+1 (same for
// A and B; reduction order-invariant) so each fragment load is one lds.64.
// ---------------------------------------------------------------------------
__device__ __forceinline__ void load_stage(uint32_t stage_base,
                                           const float* __restrict__ A,
                                           const float* __restrict__ B,
                                           int bm, int bn, int K, int k0, int tid)
{
    const int row = tid >> 3;            // 0..31
    const int c4  = tid & 7;             // 0..7
    const float* Ap = A + (size_t)(bm + row) * K + k0 + c4 * 4;
    const float* Bp = B + (size_t)(bn + row) * K + k0 + c4 * 4;
    uint32_t dstA = stage_base + (row * ASTRIDE + c4 * 4) * 4;
    uint32_t dstB = stage_base + TILE_A_BYTES + (row * ASTRIDE + c4 * 4) * 4;
    #pragma unroll
    for (int i = 0; i < 4; i++)          // A: 128 rows
        cp16(dstA + i * 32 * ASTRIDE * 4, Ap + (size_t)(i * 32) * K);
    #pragma unroll
    for (int i = 0; i < 8; i++)          // B: 256 rows
        cp16(dstB + i * 32 * ASTRIDE * 4, Bp + (size_t)(i * 32) * K);
}

__global__ void __launch_bounds__(256)
gemm_tc_kernel(const float* __restrict__ A, const float* __restrict__ B,
               const float* __restrict__ bias, float* __restrict__ C,
               int M, int N, int K)
{
    extern __shared__ char smraw[];
    const uint32_t smem_base = smem_u32(smraw);
    const int tid  = threadIdx.x;
    const int wid  = tid >> 5;
    const int lane = tid & 31;
    const int g    = lane >> 2;          // 0..7
    const int t    = lane & 3;           // 0..3
    const int wm   = wid >> 2;           // 0..1
    const int wn   = wid & 3;            // 0..3
    const int bm   = blockIdx.y * BM;
    const int bn   = blockIdx.x * BN;

    float acc[4][8][4];
    #pragma unroll
    for (int mi = 0; mi < 4; mi++)
        #pragma unroll
        for (int ni = 0; ni < 8; ni++)
            #pragma unroll
            for (int r = 0; r < 4; r++) acc[mi][ni][r] = 0.f;

    const int KT = K / BK;

    #pragma unroll
    for (int s = 0; s < NS - 1; s++) {
        load_stage(smem_base + s * STAGE_BYTES, A, B, bm, bn, K, s * BK, tid);
        CP_COMMIT();
    }

    const uint32_t a_base = ((wm * 64 + g) * ASTRIDE + 2 * t) * 4;
    const uint32_t b_base = TILE_A_BYTES + ((wn * 64 + g) * ASTRIDE + 2 * t) * 4;

    int cmp_s = 0;           // stage being computed
    int ld_s  = NS - 1;      // stage being loaded
    for (int kt = 0; kt < KT; kt++) {
        CP_WAIT(NS - 2);
        __syncthreads();

        if (kt + NS - 1 < KT)
            load_stage(smem_base + ld_s * STAGE_BYTES, A, B, bm, bn, K,
                       (kt + NS - 1) * BK, tid);
        CP_COMMIT();
        ld_s = (ld_s + 1 == NS) ? 0 : ld_s + 1;

        const uint32_t stage = smem_base + cmp_s * STAGE_BYTES;
        cmp_s = (cmp_s + 1 == NS) ? 0 : cmp_s + 1;

        #pragma unroll
        for (int kk = 0; kk < 4; kk++) {
            const uint32_t koff = kk * 8 * 4;
            uint32_t bf[8][2];
            #pragma unroll
            for (int ni = 0; ni < 8; ni++) {
                const uint32_t bb = stage + b_base + ni * 8 * ASTRIDE * 4 + koff;
                lds64(bf[ni][0], bf[ni][1], bb);
            }
            #pragma unroll
            for (int mi = 0; mi < 4; mi++) {
                uint32_t af[4];
                const uint32_t ab = stage + a_base + mi * 16 * ASTRIDE * 4 + koff;
                lds64(af[0], af[2], ab);
                lds64(af[1], af[3], ab + 8 * ASTRIDE * 4);
                #pragma unroll
                for (int ni = 0; ni < 8; ni++)
                    mma_tf32(acc[mi][ni], af, bf[ni]);
            }
        }
    }

    // Epilogue: bias add + store
    #pragma unroll
    for (int mi = 0; mi < 4; mi++) {
        const int row0 = bm + wm * 64 + mi * 16 + g;
        #pragma unroll
        for (int ni = 0; ni < 8; ni++) {
            const int col = bn + wn * 64 + ni * 8 + 2 * t;
            const float2 bb = __ldg((const float2*)&bias[col]);
            float2 o0, o1;
            o0.x = acc[mi][ni][0] + bb.x;
            o0.y = acc[mi][ni][1] + bb.y;
            o1.x = acc[mi][ni][2] + bb.x;
            o1.y = acc[mi][ni][3] + bb.y;
            *(float2*)&C[(size_t)row0 * N + col]       = o0;
            *(float2*)&C[(size_t)(row0 + 8) * N + col] = o1;
        }
    }
}

// ---------------------------------------------------------------------------
// RoPE, in place on q (channel 0) and k (channel 1) of g_qkv.
// ---------------------------------------------------------------------------
__global__ void rope_kernel(float* __restrict__ qkv,
                            const float* __restrict__ cosT,
                            const float* __restrict__ sinT)
{
    const int total = S_TOT * NH * ROT;
    int idx = blockIdx.x * blockDim.x + threadIdx.x;
    if (idx >= total) return;

    const int j = idx % ROT;
    const int h = (idx / ROT) % NH;
    const int s = idx / (ROT * NH);

    const float c  = cosT[s * ROT + j];
    const float sn = sinT[s * ROT + j];

    size_t base = (size_t)s * QKV_N + h * HD;
    float q1 = qkv[base + j], q2 = qkv[base + ROT + j];
    qkv[base + j]       = q1 * c - q2 * sn;
    qkv[base + ROT + j] = q2 * c + q1 * sn;

    base += HID;
    float k1 = qkv[base + j], k2 = qkv[base + ROT + j];
    qkv[base + j]       = k1 * c - k2 * sn;
    qkv[base + ROT + j] = k2 * c + k1 * sn;
}

// ---------------------------------------------------------------------------
// Windowed attention: one block per (window, head). 256 threads.
// Register-tiled: QK 4x4/thread, PV 4x5/thread, warp-parallel softmax.
// Output written tf32-rounded (feeds proj GEMM).
// smem: q[64*81] k[64*81] v[64*80] sc[64*64] = 78336 B
// ---------------------------------------------------------------------------
#define ATTN_SMEM ((WIN * 81 * 2 + WIN * HD + WIN * WIN) * 4)

__global__ void __launch_bounds__(256)
attn_kernel(const float* __restrict__ qkv, float* __restrict__ outp)
{
    extern __shared__ float smf[];
    float* qs = smf;                    // 64*81
    float* ks = smf + WIN * 81;         // 64*81
    float* vs = ks + WIN * 81;          // 64*80
    float* sc = vs + WIN * HD;          // 64*64

    const int tid = threadIdx.x;
    const int w   = blockIdx.x >> 4;
    const int h   = blockIdx.x & 15;
    const int s0  = w * WIN;

    for (int i = tid; i < WIN * HD; i += 256) {
        const int r = i / HD, d = i % HD;
        const size_t rb = (size_t)(s0 + r) * QKV_N + h * HD + d;
        qs[r * 81 + d] = qkv[rb];
        ks[r * 81 + d] = qkv[rb + HID];
        vs[r * HD + d] = qkv[rb + 2 * HID];
    }
    __syncthreads();

    // ---- QK^T, 4x4 register tile per thread --------------------------------
    const int qi4 = (tid >> 4) * 4;     // row base
    const int kj4 = (tid & 15) * 4;     // col base
    {
        float s4[4][4];
        #pragma unroll
        for (int i = 0; i < 4; i++)
            #pragma unroll
            for (int j = 0; j < 4; j++) s4[i][j] = 0.f;

        for (int d = 0; d < HD; d += 4) {
            #pragma unroll
            for (int dd = 0; dd < 4; dd++) {
                float qv[4], kv[4];
                #pragma unroll
                for (int i = 0; i < 4; i++) qv[i] = qs[(qi4 + i) * 81 + d + dd];
                #pragma unroll
                for (int j = 0; j < 4; j++) kv[j] = ks[(kj4 + j) * 81 + d + dd];
                #pragma unroll
                for (int i = 0; i < 4; i++)
                    #pragma unroll
                    for (int j = 0; j < 4; j++)
                        s4[i][j] += qv[i] * kv[j];
            }
        }
        const float scale = 0.11180339887498949f;   // 1/sqrt(80)
        #pragma unroll
        for (int i = 0; i < 4; i++) {
            float4 o = make_float4(s4[i][0] * scale, s4[i][1] * scale,
                                   s4[i][2] * scale, s4[i][3] * scale);
            *(float4*)&sc[(qi4 + i) * WIN + kj4] = o;
        }
    }
    __syncthreads();

    // ---- softmax: warp wr handles rows 8*wr..8*wr+7 ------------------------
    {
        const int wr = tid >> 5, lane = tid & 31;
        #pragma unroll
        for (int r8 = 0; r8 < 8; r8++) {
            const int row = wr * 8 + r8;
            float v0 = sc[row * WIN + lane];
            float v1 = sc[row * WIN + lane + 32];
            float m = fmaxf(v0, v1);
            #pragma unroll
            for (int o = 16; o; o >>= 1) m = fmaxf(m, __shfl_xor_sync(~0u, m, o));
            float e0 = __expf(v0 - m), e1 = __expf(v1 - m);
            float s = e0 + e1;
            #pragma unroll
            for (int o = 16; o; o >>= 1) s += __shfl_xor_sync(~0u, s, o);
            const float inv = 1.f / s;
            sc[row * WIN + lane]      = e0 * inv;
            sc[row * WIN + lane + 32] = e1 * inv;
        }
    }
    __syncthreads();

    // ---- PV: rows qi4..+3, dims dg..+4 per thread --------------------------
    {
        const int dg = (tid & 15) * 5;   // 0..75
        float o[4][5];
        #pragma unroll
        for (int i = 0; i < 4; i++)
            #pragma unroll
            for (int u = 0; u < 5; u++) o[i][u] = 0.f;

        for (int kj = 0; kj < WIN; kj += 4) {
            #pragma unroll
            for (int jj = 0; jj < 4; jj++) {
                float p[4], vv[5];
                #pragma unroll
                for (int i = 0; i < 4; i++) p[i] = sc[(qi4 + i) * WIN + kj + jj];
                #pragma unroll
                for (int u = 0; u < 5; u++) vv[u] = vs[(kj + jj) * HD + dg + u];
                #pragma unroll
                for (int i = 0; i < 4; i++)
                    #pragma unroll
                    for (int u = 0; u < 5; u++)
                        o[i][u] += p[i] * vv[u];
            }
        }
        #pragma unroll
        for (int i = 0; i < 4; i++) {
            float* op = outp + (size_t)(s0 + qi4 + i) * HID + h * HD + dg;
            #pragma unroll
            for (int u = 0; u < 5; u++) op[u] = tf32r(o[i][u]);
        }
    }
}

// ---------------------------------------------------------------------------
// Launch
// ---------------------------------------------------------------------------
extern "C" void kernel_launch(void* const* d_in, const int* in_sizes, int n_in,
                              void* d_out, int out_size)
{
    const float* x      = (const float*)d_in[0];
    const float* cosT   = (const float*)d_in[1];
    const float* sinT   = (const float*)d_in[2];
    const float* qkv_w  = (const float*)d_in[3];
    const float* qkv_b  = (const float*)d_in[4];
    const float* proj_w = (const float*)d_in[5];
    const float* proj_b = (const float*)d_in[6];
    float* out = (float*)d_out;

    float *qkv, *attn, *xr, *wr, *pwr;
    cudaGetSymbolAddress((void**)&qkv,  g_qkv);
    cudaGetSymbolAddress((void**)&attn, g_attn);
    cudaGetSymbolAddress((void**)&xr,   g_xr);
    cudaGetSymbolAddress((void**)&wr,   g_wr);
    cudaGetSymbolAddress((void**)&pwr,  g_pwr);

    cudaFuncSetAttribute(attn_kernel, cudaFuncAttributeMaxDynamicSharedMemorySize,
                         ATTN_SMEM);
    cudaFuncSetAttribute(gemm_tc_kernel, cudaFuncAttributeMaxDynamicSharedMemorySize,
                         GEMM_SMEM);

    // 0) pre-round inputs to tf32-exact fp32
    {
        int n4x = S_TOT * HID / 4;
        int n4w = QKV_N * HID / 4;
        int n4p = HID * HID / 4;
        preround_kernel<<<(n4x + 255) / 256, 256>>>((const float4*)x,    (float4*)xr,  n4x);
        preround_kernel<<<(n4w + 255) / 256, 256>>>((const float4*)qkv_w, (float4*)wr,  n4w);
        preround_kernel<<<(n4p + 255) / 256, 256>>>((const float4*)proj_w,(float4*)pwr, n4p);
    }
    // 1) QKV GEMM + bias -> g_qkv
    {
        dim3 grid(QKV_N / BN, S_TOT / BM);   // (15, 128)
        gemm_tc_kernel<<<grid, 256, GEMM_SMEM>>>(xr, wr, qkv_b, qkv,
                                                 S_TOT, QKV_N, HID);
    }
    // 2) RoPE in-place on q, k
    {
        const int total = S_TOT * NH * ROT;
        rope_kernel<<<(total + 255) / 256, 256>>>(qkv, cosT, sinT);
    }
    // 3) windowed attention -> g_attn (tf32-rounded)
    {
        attn_kernel<<<NW * NH, 256, ATTN_SMEM>>>(qkv, attn);
    }
    // 4) output projection + bias -> d_out
    {
        dim3 grid(HID / BN, S_TOT / BM);     // (5, 128)
        gemm_tc_kernel<<<grid, 256, GEMM_SMEM>>>(attn, pwr, proj_b, out,
                                                 S_TOT, HID, HID);
    }
}

// round 7
// speedup vs baseline: 5.0550x; 1.4452x over previous
#include <cuda_runtime.h>
#include <cuda_fp16.h>
#include <cstdint>

// Problem constants
#define S_TOT  16384
#define HID    1280
#define NH     16
#define HD     80
#define WIN    64
#define NW     256
#define QKV_N  3840
#define ROT    40

// fp16 mma.sync GEMM tiling: CTA 128x256, warp tile 64x64, BK=32 halves, NS=4
#define BM 128
#define BN 256
#define BK 32
#define NS 4
#define ROWB 64                                    // bytes per smem row (32 halves)
#define TILE_A_BYTES (128 * ROWB)                  // 8192
#define TILE_B_BYTES (256 * ROWB)                  // 16384
#define STAGE_BYTES  (TILE_A_BYTES + TILE_B_BYTES) // 24576
#define GEMM_SMEM    (NS * STAGE_BYTES)            // 98304 B

// ---------------------------------------------------------------------------
// Scratch (device globals: allocation-guard-safe)
// ---------------------------------------------------------------------------
__device__ float  g_qkv  [(size_t)S_TOT * QKV_N];  // 252 MB fp32
__device__ __half g_xh   [(size_t)S_TOT * HID];    // 42 MB
__device__ __half g_wh   [(size_t)QKV_N * HID];    // 9.8 MB
__device__ __half g_pwh  [(size_t)HID * HID];      // 3.3 MB
__device__ __half g_attnh[(size_t)S_TOT * HID];    // 42 MB

// ---------------------------------------------------------------------------
// PTX helpers (sm_100 base target)
// ---------------------------------------------------------------------------
__device__ __forceinline__ uint32_t smem_u32(const void* p) {
    uint32_t a;
    asm("{ .reg .u64 t; cvta.to.shared.u64 t, %1; cvt.u32.u64 %0, t; }"
        : "=r"(a) : "l"(p));
    return a;
}
__device__ __forceinline__ void cp16(uint32_t dst, const void* src) {
    asm volatile("cp.async.cg.shared.global [%0], [%1], 16;" :: "r"(dst), "l"(src));
}
#define CP_COMMIT()  asm volatile("cp.async.commit_group;" ::: "memory")
#define CP_WAIT(n)   asm volatile("cp.async.wait_group %0;" :: "n"(n) : "memory")

__device__ __forceinline__ void lds128(uint32_t* r, uint32_t addr) {
    asm volatile("ld.shared.v4.b32 {%0,%1,%2,%3}, [%4];"
                 : "=r"(r[0]), "=r"(r[1]), "=r"(r[2]), "=r"(r[3]) : "r"(addr));
}
__device__ __forceinline__ void mma_f16(float* c, uint32_t a0, uint32_t a1,
                                        uint32_t a2, uint32_t a3,
                                        uint32_t b0, uint32_t b1) {
    asm volatile(
        "mma.sync.aligned.m16n8k16.row.col.f32.f16.f16.f32 "
        "{%0,%1,%2,%3}, {%4,%5,%6,%7}, {%8,%9}, {%0,%1,%2,%3};"
        : "+f"(c[0]), "+f"(c[1]), "+f"(c[2]), "+f"(c[3])
        : "r"(a0), "r"(a1), "r"(a2), "r"(a3), "r"(b0), "r"(b1));
}

// ---------------------------------------------------------------------------
// fp32 -> fp16 convert (8 floats / thread)
// ---------------------------------------------------------------------------
__global__ void __launch_bounds__(256)
cvt_f16_kernel(const float4* __restrict__ src, uint2* __restrict__ dst, int n4)
{
    int i = blockIdx.x * blockDim.x + threadIdx.x;
    if (i < n4) {
        float4 v = src[i];
        __half2 h0 = __floats2half2_rn(v.x, v.y);
        __half2 h1 = __floats2half2_rn(v.z, v.w);
        uint2 o;
        o.x = *(const uint32_t*)&h0;
        o.y = *(const uint32_t*)&h1;
        dst[i] = o;
    }
}

// ---------------------------------------------------------------------------
// fp16 mma.sync GEMM: C[M,N] = A[M,K]*B[N,K]^T + bias[N]   (fp32 out)
// A [M,K] half row-major, B [N,K] half row-major. 256 threads, 8 warps
// (2M x 4N), warp tile 64x64. K-relabeling at read: one lds.128 per row at
// phys halves 8t..8t+7 supplies (a0,a2) [or (b0,b1)] for BOTH K=16 chunks of
// the 32-half k-tile; identical relabeling on A and B (reduction commutes).
// Smem row stride 64B -> lds.128 phases cover all 32 banks (conflict-free).
// Requires M%128==0, N%256==0, K%32==0.
// ---------------------------------------------------------------------------
__device__ __forceinline__ void load_stage(uint32_t stage_base,
                                           const __half* __restrict__ A,
                                           const __half* __restrict__ B,
                                           int bm, int bn, int K, int k0, int tid)
{
    const int row = tid >> 2;            // 0..63
    const int seg = tid & 3;             // 16B segment within 64B row
    // A: 128 rows
    #pragma unroll
    for (int i = 0; i < 2; i++) {
        const int r = row + i * 64;
        cp16(stage_base + r * ROWB + seg * 16,
             A + (size_t)(bm + r) * K + k0 + seg * 8);
    }
    // B: 256 rows
    #pragma unroll
    for (int i = 0; i < 4; i++) {
        const int r = row + i * 64;
        cp16(stage_base + TILE_A_BYTES + r * ROWB + seg * 16,
             B + (size_t)(bn + r) * K + k0 + seg * 8);
    }
}

__global__ void __launch_bounds__(256)
gemm_f16_kernel(const __half* __restrict__ A, const __half* __restrict__ B,
                const float* __restrict__ bias, float* __restrict__ C,
                int M, int N, int K)
{
    extern __shared__ char smraw[];
    const uint32_t smem_base = smem_u32(smraw);
    const int tid  = threadIdx.x;
    const int wid  = tid >> 5;
    const int lane = tid & 31;
    const int g    = lane >> 2;          // 0..7
    const int t    = lane & 3;           // 0..3
    const int wm   = wid >> 2;           // 0..1
    const int wn   = wid & 3;            // 0..3
    const int bm   = blockIdx.y * BM;
    const int bn   = blockIdx.x * BN;

    float acc[4][8][4];
    #pragma unroll
    for (int mi = 0; mi < 4; mi++)
        #pragma unroll
        for (int ni = 0; ni < 8; ni++)
            #pragma unroll
            for (int r = 0; r < 4; r++) acc[mi][ni][r] = 0.f;

    const int KT = K / BK;

    #pragma unroll
    for (int s = 0; s < NS - 1; s++) {
        load_stage(smem_base + s * STAGE_BYTES, A, B, bm, bn, K, s * BK, tid);
        CP_COMMIT();
    }

    const uint32_t a_base = (wm * 64 + g) * ROWB + t * 16;
    const uint32_t b_base = TILE_A_BYTES + (wn * 64 + g) * ROWB + t * 16;

    int cmp_s = 0, ld_s = NS - 1;
    for (int kt = 0; kt < KT; kt++) {
        CP_WAIT(NS - 2);
        __syncthreads();

        if (kt + NS - 1 < KT)
            load_stage(smem_base + ld_s * STAGE_BYTES, A, B, bm, bn, K,
                       (kt + NS - 1) * BK, tid);
        CP_COMMIT();
        ld_s = (ld_s + 1 == NS) ? 0 : ld_s + 1;

        const uint32_t stage = smem_base + cmp_s * STAGE_BYTES;
        cmp_s = (cmp_s + 1 == NS) ? 0 : cmp_s + 1;

        // B fragments for both K=16 chunks: 8 x lds.128
        uint32_t bf[8][4];
        #pragma unroll
        for (int ni = 0; ni < 8; ni++)
            lds128(bf[ni], stage + b_base + ni * 8 * ROWB);

        #pragma unroll
        for (int mi = 0; mi < 4; mi++) {
            uint32_t ar0[4], ar1[4];
            const uint32_t ab = stage + a_base + mi * 16 * ROWB;
            lds128(ar0, ab);                 // row g
            lds128(ar1, ab + 8 * ROWB);      // row g+8
            #pragma unroll
            for (int ni = 0; ni < 8; ni++) {
                mma_f16(acc[mi][ni], ar0[0], ar1[0], ar0[1], ar1[1],
                        bf[ni][0], bf[ni][1]);          // chunk 0
                mma_f16(acc[mi][ni], ar0[2], ar1[2], ar0[3], ar1[3],
                        bf[ni][2], bf[ni][3]);          // chunk 1
            }
        }
    }

    // Epilogue: bias add + fp32 store
    #pragma unroll
    for (int mi = 0; mi < 4; mi++) {
        const int row0 = bm + wm * 64 + mi * 16 + g;
        #pragma unroll
        for (int ni = 0; ni < 8; ni++) {
            const int col = bn + wn * 64 + ni * 8 + 2 * t;
            const float2 bb = __ldg((const float2*)&bias[col]);
            float2 o0, o1;
            o0.x = acc[mi][ni][0] + bb.x;
            o0.y = acc[mi][ni][1] + bb.y;
            o1.x = acc[mi][ni][2] + bb.x;
            o1.y = acc[mi][ni][3] + bb.y;
            *(float2*)&C[(size_t)row0 * N + col]       = o0;
            *(float2*)&C[(size_t)(row0 + 8) * N + col] = o1;
        }
    }
}

// ---------------------------------------------------------------------------
// RoPE, in place on q (channel 0) and k (channel 1) of g_qkv.
// ---------------------------------------------------------------------------
__global__ void rope_kernel(float* __restrict__ qkv,
                            const float* __restrict__ cosT,
                            const float* __restrict__ sinT)
{
    const int total = S_TOT * NH * ROT;
    int idx = blockIdx.x * blockDim.x + threadIdx.x;
    if (idx >= total) return;

    const int j = idx % ROT;
    const int h = (idx / ROT) % NH;
    const int s = idx / (ROT * NH);

    const float c  = cosT[s * ROT + j];
    const float sn = sinT[s * ROT + j];

    size_t base = (size_t)s * QKV_N + h * HD;
    float q1 = qkv[base + j], q2 = qkv[base + ROT + j];
    qkv[base + j]       = q1 * c - q2 * sn;
    qkv[base + ROT + j] = q2 * c + q1 * sn;

    base += HID;
    float k1 = qkv[base + j], k2 = qkv[base + ROT + j];
    qkv[base + j]       = k1 * c - k2 * sn;
    qkv[base + ROT + j] = k2 * c + k1 * sn;
}

// ---------------------------------------------------------------------------
// Windowed attention: one block per (window, head). 256 threads.
// Register-tiled: QK 4x4/thread, PV 4x5/thread, warp-parallel softmax.
// Output written fp16 (feeds proj GEMM).
// ---------------------------------------------------------------------------
#define ATTN_SMEM ((WIN * 81 * 2 + WIN * HD + WIN * WIN) * 4)

__global__ void __launch_bounds__(256)
attn_kernel(const float* __restrict__ qkv, __half* __restrict__ outp)
{
    extern __shared__ float smf[];
    float* qs = smf;                    // 64*81
    float* ks = smf + WIN * 81;         // 64*81
    float* vs = ks + WIN * 81;          // 64*80
    float* sc = vs + WIN * HD;          // 64*64

    const int tid = threadIdx.x;
    const int w   = blockIdx.x >> 4;
    const int h   = blockIdx.x & 15;
    const int s0  = w * WIN;

    for (int i = tid; i < WIN * HD; i += 256) {
        const int r = i / HD, d = i % HD;
        const size_t rb = (size_t)(s0 + r) * QKV_N + h * HD + d;
        qs[r * 81 + d] = qkv[rb];
        ks[r * 81 + d] = qkv[rb + HID];
        vs[r * HD + d] = qkv[rb + 2 * HID];
    }
    __syncthreads();

    const int qi4 = (tid >> 4) * 4;
    const int kj4 = (tid & 15) * 4;
    {
        float s4[4][4];
        #pragma unroll
        for (int i = 0; i < 4; i++)
            #pragma unroll
            for (int j = 0; j < 4; j++) s4[i][j] = 0.f;

        for (int d = 0; d < HD; d += 4) {
            #pragma unroll
            for (int dd = 0; dd < 4; dd++) {
                float qv[4], kv[4];
                #pragma unroll
                for (int i = 0; i < 4; i++) qv[i] = qs[(qi4 + i) * 81 + d + dd];
                #pragma unroll
                for (int j = 0; j < 4; j++) kv[j] = ks[(kj4 + j) * 81 + d + dd];
                #pragma unroll
                for (int i = 0; i < 4; i++)
                    #pragma unroll
                    for (int j = 0; j < 4; j++)
                        s4[i][j] += qv[i] * kv[j];
            }
        }
        const float scale = 0.11180339887498949f;
        #pragma unroll
        for (int i = 0; i < 4; i++) {
            float4 o = make_float4(s4[i][0] * scale, s4[i][1] * scale,
                                   s4[i][2] * scale, s4[i][3] * scale);
            *(float4*)&sc[(qi4 + i) * WIN + kj4] = o;
        }
    }
    __syncthreads();

    {
        const int wr = tid >> 5, lane = tid & 31;
        #pragma unroll
        for (int r8 = 0; r8 < 8; r8++) {
            const int row = wr * 8 + r8;
            float v0 = sc[row * WIN + lane];
            float v1 = sc[row * WIN + lane + 32];
            float m = fmaxf(v0, v1);
            #pragma unroll
            for (int o = 16; o; o >>= 1) m = fmaxf(m, __shfl_xor_sync(~0u, m, o));
            float e0 = __expf(v0 - m), e1 = __expf(v1 - m);
            float s = e0 + e1;
            #pragma unroll
            for (int o = 16; o; o >>= 1) s += __shfl_xor_sync(~0u, s, o);
            const float inv = 1.f / s;
            sc[row * WIN + lane]      = e0 * inv;
            sc[row * WIN + lane + 32] = e1 * inv;
        }
    }
    __syncthreads();

    {
        const int dg = (tid & 15) * 5;
        float o[4][5];
        #pragma unroll
        for (int i = 0; i < 4; i++)
            #pragma unroll
            for (int u = 0; u < 5; u++) o[i][u] = 0.f;

        for (int kj = 0; kj < WIN; kj += 4) {
            #pragma unroll
            for (int jj = 0; jj < 4; jj++) {
                float p[4], vv[5];
                #pragma unroll
                for (int i = 0; i < 4; i++) p[i] = sc[(qi4 + i) * WIN + kj + jj];
                #pragma unroll
                for (int u = 0; u < 5; u++) vv[u] = vs[(kj + jj) * HD + dg + u];
                #pragma unroll
                for (int i = 0; i < 4; i++)
                    #pragma unroll
                    for (int u = 0; u < 5; u++)
                        o[i][u] += p[i] * vv[u];
            }
        }
        #pragma unroll
        for (int i = 0; i < 4; i++) {
            __half* op = outp + (size_t)(s0 + qi4 + i) * HID + h * HD + dg;
            #pragma unroll
            for (int u = 0; u < 5; u++) op[u] = __float2half_rn(o[i][u]);
        }
    }
}

// ---------------------------------------------------------------------------
// Launch
// ---------------------------------------------------------------------------
extern "C" void kernel_launch(void* const* d_in, const int* in_sizes, int n_in,
                              void* d_out, int out_size)
{
    const float* x      = (const float*)d_in[0];
    const float* cosT   = (const float*)d_in[1];
    const float* sinT   = (const float*)d_in[2];
    const float* qkv_w  = (const float*)d_in[3];
    const float* qkv_b  = (const float*)d_in[4];
    const float* proj_w = (const float*)d_in[5];
    const float* proj_b = (const float*)d_in[6];
    float* out = (float*)d_out;

    float *qkv;
    __half *xh, *wh, *pwh, *attnh;
    cudaGetSymbolAddress((void**)&qkv,   g_qkv);
    cudaGetSymbolAddress((void**)&xh,    g_xh);
    cudaGetSymbolAddress((void**)&wh,    g_wh);
    cudaGetSymbolAddress((void**)&pwh,   g_pwh);
    cudaGetSymbolAddress((void**)&attnh, g_attnh);

    cudaFuncSetAttribute(attn_kernel, cudaFuncAttributeMaxDynamicSharedMemorySize,
                         ATTN_SMEM);
    cudaFuncSetAttribute(gemm_f16_kernel, cudaFuncAttributeMaxDynamicSharedMemorySize,
                         GEMM_SMEM);

    // 0) convert inputs to fp16
    {
        int n4x = S_TOT * HID / 4;
        int n4w = QKV_N * HID / 4;
        int n4p = HID * HID / 4;
        cvt_f16_kernel<<<(n4x + 255) / 256, 256>>>((const float4*)x,     (uint2*)xh,  n4x);
        cvt_f16_kernel<<<(n4w + 255) / 256, 256>>>((const float4*)qkv_w, (uint2*)wh,  n4w);
        cvt_f16_kernel<<<(n4p + 255) / 256, 256>>>((const float4*)proj_w,(uint2*)pwh, n4p);
    }
    // 1) QKV GEMM + bias -> g_qkv (fp32)
    {
        dim3 grid(QKV_N / BN, S_TOT / BM);   // (15, 128)
        gemm_f16_kernel<<<grid, 256, GEMM_SMEM>>>(xh, wh, qkv_b, qkv,
                                                  S_TOT, QKV_N, HID);
    }
    // 2) RoPE in-place on q, k
    {
        const int total = S_TOT * NH * ROT;
        rope_kernel<<<(total + 255) / 256, 256>>>(qkv, cosT, sinT);
    }
    // 3) windowed attention -> g_attnh (fp16)
    {
        attn_kernel<<<NW * NH, 256, ATTN_SMEM>>>(qkv, attnh);
    }
    // 4) output projection + bias -> d_out (fp32)
    {
        dim3 grid(HID / BN, S_TOT / BM);     // (5, 128)
        gemm_f16_kernel<<<grid, 256, GEMM_SMEM>>>(attnh, pwh, proj_b, out,
                                                  S_TOT, HID, HID);
    }
}

// round 9
// speedup vs baseline: 6.5731x; 1.3003x over previous
#include <cuda_runtime.h>
#include <cuda_fp16.h>
#include <cstdint>

// Problem constants
#define S_TOT  16384
#define HID    1280
#define NH     16
#define HD     80
#define WIN    64
#define NW     256
#define QKV_N  3840
#define ROT    40

// fp16 mma.sync GEMM tiling: CTA 128x256, warp tile 64x64, BK=32 halves, NS=4
#define BM 128
#define BN 256
#define BK 32
#define NS 4
#define ROWB 64
#define TILE_A_BYTES (128 * ROWB)
#define TILE_B_BYTES (256 * ROWB)
#define STAGE_BYTES  (TILE_A_BYTES + TILE_B_BYTES)
#define GEMM_SMEM    (NS * STAGE_BYTES)            // 98304 B

// attention smem strides (halves), conflict-free ldmatrix, 16B-aligned rows
#define AT_QS 88
#define AT_VS 72

// ---------------------------------------------------------------------------
// Scratch (device globals: allocation-guard-safe)
// ---------------------------------------------------------------------------
__device__ float  g_qkv  [(size_t)S_TOT * QKV_N];  // 252 MB fp32
__device__ __half g_xh   [(size_t)S_TOT * HID];
__device__ __half g_wh   [(size_t)QKV_N * HID];
__device__ __half g_pwh  [(size_t)HID * HID];
__device__ __half g_attnh[(size_t)S_TOT * HID];

// ---------------------------------------------------------------------------
// PTX helpers (sm_100 base target)
// ---------------------------------------------------------------------------
__device__ __forceinline__ uint32_t smem_u32(const void* p) {
    uint32_t a;
    asm("{ .reg .u64 t; cvta.to.shared.u64 t, %1; cvt.u32.u64 %0, t; }"
        : "=r"(a) : "l"(p));
    return a;
}
__device__ __forceinline__ void cp16(uint32_t dst, const void* src) {
    asm volatile("cp.async.cg.shared.global [%0], [%1], 16;" :: "r"(dst), "l"(src));
}
#define CP_COMMIT()  asm volatile("cp.async.commit_group;" ::: "memory")
#define CP_WAIT(n)   asm volatile("cp.async.wait_group %0;" :: "n"(n) : "memory")

__device__ __forceinline__ void lds128(uint32_t* r, uint32_t addr) {
    asm volatile("ld.shared.v4.b32 {%0,%1,%2,%3}, [%4];"
                 : "=r"(r[0]), "=r"(r[1]), "=r"(r[2]), "=r"(r[3]) : "r"(addr));
}
__device__ __forceinline__ void ldsm4(uint32_t* r, uint32_t addr) {
    asm volatile("ldmatrix.sync.aligned.m8n8.x4.shared.b16 {%0,%1,%2,%3}, [%4];"
                 : "=r"(r[0]), "=r"(r[1]), "=r"(r[2]), "=r"(r[3]) : "r"(addr));
}
__device__ __forceinline__ void mma_f16(float* c, uint32_t a0, uint32_t a1,
                                        uint32_t a2, uint32_t a3,
                                        uint32_t b0, uint32_t b1) {
    asm volatile(
        "mma.sync.aligned.m16n8k16.row.col.f32.f16.f16.f32 "
        "{%0,%1,%2,%3}, {%4,%5,%6,%7}, {%8,%9}, {%0,%1,%2,%3};"
        : "+f"(c[0]), "+f"(c[1]), "+f"(c[2]), "+f"(c[3])
        : "r"(a0), "r"(a1), "r"(a2), "r"(a3), "r"(b0), "r"(b1));
}

// ---------------------------------------------------------------------------
// fp32 -> fp16 convert
// ---------------------------------------------------------------------------
__global__ void __launch_bounds__(256)
cvt_f16_kernel(const float4* __restrict__ src, uint2* __restrict__ dst, int n4)
{
    int i = blockIdx.x * blockDim.x + threadIdx.x;
    if (i < n4) {
        float4 v = src[i];
        __half2 h0 = __floats2half2_rn(v.x, v.y);
        __half2 h1 = __floats2half2_rn(v.z, v.w);
        uint2 o;
        o.x = *(const uint32_t*)&h0;
        o.y = *(const uint32_t*)&h1;
        dst[i] = o;
    }
}

// ---------------------------------------------------------------------------
// fp16 mma.sync GEMM: C = A*B^T + bias, fp32 out (validated R7)
// ---------------------------------------------------------------------------
__device__ __forceinline__ void load_stage(uint32_t stage_base,
                                           const __half* __restrict__ A,
                                           const __half* __restrict__ B,
                                           int bm, int bn, int K, int k0, int tid)
{
    const int row = tid >> 2;
    const int seg = tid & 3;
    #pragma unroll
    for (int i = 0; i < 2; i++) {
        const int r = row + i * 64;
        cp16(stage_base + r * ROWB + seg * 16,
             A + (size_t)(bm + r) * K + k0 + seg * 8);
    }
    #pragma unroll
    for (int i = 0; i < 4; i++) {
        const int r = row + i * 64;
        cp16(stage_base + TILE_A_BYTES + r * ROWB + seg * 16,
             B + (size_t)(bn + r) * K + k0 + seg * 8);
    }
}

__global__ void __launch_bounds__(256)
gemm_f16_kernel(const __half* __restrict__ A, const __half* __restrict__ B,
                const float* __restrict__ bias, float* __restrict__ C,
                int M, int N, int K)
{
    extern __shared__ char smraw[];
    const uint32_t smem_base = smem_u32(smraw);
    const int tid  = threadIdx.x;
    const int wid  = tid >> 5;
    const int lane = tid & 31;
    const int g    = lane >> 2;
    const int t    = lane & 3;
    const int wm   = wid >> 2;
    const int wn   = wid & 3;
    const int bm   = blockIdx.y * BM;
    const int bn   = blockIdx.x * BN;

    float acc[4][8][4];
    #pragma unroll
    for (int mi = 0; mi < 4; mi++)
        #pragma unroll
        for (int ni = 0; ni < 8; ni++)
            #pragma unroll
            for (int r = 0; r < 4; r++) acc[mi][ni][r] = 0.f;

    const int KT = K / BK;

    #pragma unroll
    for (int s = 0; s < NS - 1; s++) {
        load_stage(smem_base + s * STAGE_BYTES, A, B, bm, bn, K, s * BK, tid);
        CP_COMMIT();
    }

    const uint32_t a_base = (wm * 64 + g) * ROWB + t * 16;
    const uint32_t b_base = TILE_A_BYTES + (wn * 64 + g) * ROWB + t * 16;

    int cmp_s = 0, ld_s = NS - 1;
    for (int kt = 0; kt < KT; kt++) {
        CP_WAIT(NS - 2);
        __syncthreads();

        if (kt + NS - 1 < KT)
            load_stage(smem_base + ld_s * STAGE_BYTES, A, B, bm, bn, K,
                       (kt + NS - 1) * BK, tid);
        CP_COMMIT();
        ld_s = (ld_s + 1 == NS) ? 0 : ld_s + 1;

        const uint32_t stage = smem_base + cmp_s * STAGE_BYTES;
        cmp_s = (cmp_s + 1 == NS) ? 0 : cmp_s + 1;

        uint32_t bf[8][4];
        #pragma unroll
        for (int ni = 0; ni < 8; ni++)
            lds128(bf[ni], stage + b_base + ni * 8 * ROWB);

        #pragma unroll
        for (int mi = 0; mi < 4; mi++) {
            uint32_t ar0[4], ar1[4];
            const uint32_t ab = stage + a_base + mi * 16 * ROWB;
            lds128(ar0, ab);
            lds128(ar1, ab + 8 * ROWB);
            #pragma unroll
            for (int ni = 0; ni < 8; ni++) {
                mma_f16(acc[mi][ni], ar0[0], ar1[0], ar0[1], ar1[1],
                        bf[ni][0], bf[ni][1]);
                mma_f16(acc[mi][ni], ar0[2], ar1[2], ar0[3], ar1[3],
                        bf[ni][2], bf[ni][3]);
            }
        }
    }

    #pragma unroll
    for (int mi = 0; mi < 4; mi++) {
        const int row0 = bm + wm * 64 + mi * 16 + g;
        #pragma unroll
        for (int ni = 0; ni < 8; ni++) {
            const int col = bn + wn * 64 + ni * 8 + 2 * t;
            const float2 bb = __ldg((const float2*)&bias[col]);
            float2 o0, o1;
            o0.x = acc[mi][ni][0] + bb.x;
            o0.y = acc[mi][ni][1] + bb.y;
            o1.x = acc[mi][ni][2] + bb.x;
            o1.y = acc[mi][ni][3] + bb.y;
            *(float2*)&C[(size_t)row0 * N + col]       = o0;
            *(float2*)&C[(size_t)(row0 + 8) * N + col] = o1;
        }
    }
}

// ---------------------------------------------------------------------------
// Tensor-core windowed attention with fused RoPE.
// One CTA (128 thr, 4 warps) per (window, head). Warp w owns q-rows 16w..16w+15.
// QK^T via ldmatrix + m16n8k16; softmax in registers (quad shfl);
// P stays in registers (QK C-frag == PV A-frag); PV from transposed V in smem.
// ---------------------------------------------------------------------------
__global__ void __launch_bounds__(128)
attn_mma_kernel(const float* __restrict__ qkv,
                const float* __restrict__ cosT,
                const float* __restrict__ sinT,
                __half* __restrict__ outp)
{
    __shared__ __align__(16) __half smQ [WIN * AT_QS];
    __shared__ __align__(16) __half smK [WIN * AT_QS];
    __shared__ __align__(16) __half smVt[HD * AT_VS];

    const int tid = threadIdx.x;
    const int w   = blockIdx.x >> 4;
    const int h   = blockIdx.x & 15;
    const int s0  = w * WIN;
    const float scale = 0.11180339887498949f;   // 1/sqrt(80)

    // ---- load q,k with RoPE (q pre-scaled), V transposed ------------------
    for (int i = tid; i < WIN * ROT; i += 128) {
        const int r = i / ROT, j = i % ROT;
        const size_t base = (size_t)(s0 + r) * QKV_N + h * HD;
        const float c  = cosT[(s0 + r) * ROT + j];
        const float sn = sinT[(s0 + r) * ROT + j];
        const float q1 = qkv[base + j],       q2 = qkv[base + j + ROT];
        smQ[r * AT_QS + j]       = __float2half_rn((q1 * c - q2 * sn) * scale);
        smQ[r * AT_QS + j + ROT] = __float2half_rn((q2 * c + q1 * sn) * scale);
        const float k1 = qkv[base + HID + j], k2 = qkv[base + HID + j + ROT];
        smK[r * AT_QS + j]       = __float2half_rn(k1 * c - k2 * sn);
        smK[r * AT_QS + j + ROT] = __float2half_rn(k2 * c + k1 * sn);
    }
    for (int i = tid; i < WIN * HD; i += 128) {
        const int r = i / HD, d = i % HD;
        smVt[d * AT_VS + r] =
            __float2half_rn(qkv[(size_t)(s0 + r) * QKV_N + 2 * HID + h * HD + d]);
    }
    __syncthreads();

    const int wid  = tid >> 5;
    const int lane = tid & 31;
    const int g    = lane >> 2;
    const int t    = lane & 3;
    const int l8   = lane & 7;
    const int sel  = lane >> 3;

    const uint32_t qb = smem_u32(smQ);
    const uint32_t kb = smem_u32(smK);
    const uint32_t vb = smem_u32(smVt);

    // ldmatrix lane->matrix maps
    const uint32_t a_row  = (uint32_t)(wid * 16 + (sel & 1) * 8 + l8);
    const uint32_t a_coff = (uint32_t)((sel >> 1) * 8);
    const uint32_t b_roff = (uint32_t)((sel >> 1) * 8 + l8);
    const uint32_t b_coff = (uint32_t)((sel & 1) * 8);

    // ---- QK^T: scores c[8][4] ---------------------------------------------
    float c[8][4];
    #pragma unroll
    for (int j = 0; j < 8; j++)
        #pragma unroll
        for (int r = 0; r < 4; r++) c[j][r] = 0.f;

    #pragma unroll
    for (int kc = 0; kc < 5; kc++) {
        uint32_t a[4];
        ldsm4(a, qb + (a_row * AT_QS + kc * 16 + a_coff) * 2);
        #pragma unroll
        for (int np = 0; np < 4; np++) {
            uint32_t b[4];
            ldsm4(b, kb + ((np * 16 + b_roff) * AT_QS + kc * 16 + b_coff) * 2);
            mma_f16(c[2 * np],     a[0], a[1], a[2], a[3], b[0], b[1]);
            mma_f16(c[2 * np + 1], a[0], a[1], a[2], a[3], b[2], b[3]);
        }
    }

    // ---- softmax in registers ---------------------------------------------
    float m0 = -1e30f, m1 = -1e30f;
    #pragma unroll
    for (int j = 0; j < 8; j++) {
        m0 = fmaxf(m0, fmaxf(c[j][0], c[j][1]));
        m1 = fmaxf(m1, fmaxf(c[j][2], c[j][3]));
    }
    m0 = fmaxf(m0, __shfl_xor_sync(~0u, m0, 1));
    m0 = fmaxf(m0, __shfl_xor_sync(~0u, m0, 2));
    m1 = fmaxf(m1, __shfl_xor_sync(~0u, m1, 1));
    m1 = fmaxf(m1, __shfl_xor_sync(~0u, m1, 2));

    float su0 = 0.f, su1 = 0.f;
    #pragma unroll
    for (int j = 0; j < 8; j++) {
        c[j][0] = __expf(c[j][0] - m0);
        c[j][1] = __expf(c[j][1] - m0);
        c[j][2] = __expf(c[j][2] - m1);
        c[j][3] = __expf(c[j][3] - m1);
        su0 += c[j][0] + c[j][1];
        su1 += c[j][2] + c[j][3];
    }
    su0 += __shfl_xor_sync(~0u, su0, 1);
    su0 += __shfl_xor_sync(~0u, su0, 2);
    su1 += __shfl_xor_sync(~0u, su1, 1);
    su1 += __shfl_xor_sync(~0u, su1, 2);
    const float inv0 = 1.f / su0, inv1 = 1.f / su1;

    // ---- P as PV A-fragments ----------------------------------------------
    uint32_t ap[4][4];
    #pragma unroll
    for (int j2 = 0; j2 < 4; j2++) {
        __half2 h0 = __floats2half2_rn(c[2 * j2][0] * inv0,     c[2 * j2][1] * inv0);
        __half2 h1 = __floats2half2_rn(c[2 * j2][2] * inv1,     c[2 * j2][3] * inv1);
        __half2 h2 = __floats2half2_rn(c[2 * j2 + 1][0] * inv0, c[2 * j2 + 1][1] * inv0);
        __half2 h3 = __floats2half2_rn(c[2 * j2 + 1][2] * inv1, c[2 * j2 + 1][3] * inv1);
        ap[j2][0] = *(uint32_t*)&h0;
        ap[j2][1] = *(uint32_t*)&h1;
        ap[j2][2] = *(uint32_t*)&h2;
        ap[j2][3] = *(uint32_t*)&h3;
    }

    // ---- PV ---------------------------------------------------------------
    float o[10][4];
    #pragma unroll
    for (int nt = 0; nt < 10; nt++)
        #pragma unroll
        for (int r = 0; r < 4; r++) o[nt][r] = 0.f;

    #pragma unroll
    for (int j2 = 0; j2 < 4; j2++) {
        #pragma unroll
        for (int dp = 0; dp < 5; dp++) {
            uint32_t b[4];
            ldsm4(b, vb + ((dp * 16 + b_roff) * AT_VS + j2 * 16 + b_coff) * 2);
            mma_f16(o[2 * dp],     ap[j2][0], ap[j2][1], ap[j2][2], ap[j2][3],
                    b[0], b[1]);
            mma_f16(o[2 * dp + 1], ap[j2][0], ap[j2][1], ap[j2][2], ap[j2][3],
                    b[2], b[3]);
        }
    }

    // ---- store fp16 output ------------------------------------------------
    const int row0 = s0 + wid * 16 + g;
    #pragma unroll
    for (int nt = 0; nt < 10; nt++) {
        const int d = nt * 8 + 2 * t;
        __half2 lo = __floats2half2_rn(o[nt][0], o[nt][1]);
        __half2 hi = __floats2half2_rn(o[nt][2], o[nt][3]);
        *(__half2*)&outp[(size_t)row0 * HID + h * HD + d]       = lo;
        *(__half2*)&outp[(size_t)(row0 + 8) * HID + h * HD + d] = hi;
    }
}

// ---------------------------------------------------------------------------
// Launch
// ---------------------------------------------------------------------------
extern "C" void kernel_launch(void* const* d_in, const int* in_sizes, int n_in,
                              void* d_out, int out_size)
{
    const float* x      = (const float*)d_in[0];
    const float* cosT   = (const float*)d_in[1];
    const float* sinT   = (const float*)d_in[2];
    const float* qkv_w  = (const float*)d_in[3];
    const float* qkv_b  = (const float*)d_in[4];
    const float* proj_w = (const float*)d_in[5];
    const float* proj_b = (const float*)d_in[6];
    float* out = (float*)d_out;

    float *qkv;
    __half *xh, *wh, *pwh, *attnh;
    cudaGetSymbolAddress((void**)&qkv,   g_qkv);
    cudaGetSymbolAddress((void**)&xh,    g_xh);
    cudaGetSymbolAddress((void**)&wh,    g_wh);
    cudaGetSymbolAddress((void**)&pwh,   g_pwh);
    cudaGetSymbolAddress((void**)&attnh, g_attnh);

    cudaFuncSetAttribute(gemm_f16_kernel, cudaFuncAttributeMaxDynamicSharedMemorySize,
                         GEMM_SMEM);

    // 0) convert inputs to fp16
    {
        int n4x = S_TOT * HID / 4;
        int n4w = QKV_N * HID / 4;
        int n4p = HID * HID / 4;
        cvt_f16_kernel<<<(n4x + 255) / 256, 256>>>((const float4*)x,     (uint2*)xh,  n4x);
        cvt_f16_kernel<<<(n4w + 255) / 256, 256>>>((const float4*)qkv_w, (uint2*)wh,  n4w);
        cvt_f16_kernel<<<(n4p + 255) / 256, 256>>>((const float4*)proj_w,(uint2*)pwh, n4p);
    }
    // 1) QKV GEMM + bias -> g_qkv (fp32)
    {
        dim3 grid(QKV_N / BN, S_TOT / BM);
        gemm_f16_kernel<<<grid, 256, GEMM_SMEM>>>(xh, wh, qkv_b, qkv,
                                                  S_TOT, QKV_N, HID);
    }
    // 2) tensor-core attention with fused RoPE -> g_attnh (fp16)
    {
        attn_mma_kernel<<<NW * NH, 128>>>(qkv, cosT, sinT, attnh);
    }
    // 3) output projection + bias -> d_out (fp32)
    {
        dim3 grid(HID / BN, S_TOT / BM);
        gemm_f16_kernel<<<grid, 256, GEMM_SMEM>>>(attnh, pwh, proj_b, out,
                                                  S_TOT, HID, HID);
    }
}

// round 10
// speedup vs baseline: 7.1606x; 1.0894x over previous
#include <cuda_runtime.h>
#include <cuda_fp16.h>
#include <cstdint>

// Problem constants
#define S_TOT  16384
#define HID    1280
#define NH     16
#define HD     80
#define WIN    64
#define NW     256
#define QKV_N  3840
#define ROT    40

// fp16 mma.sync GEMM tiling: CTA 128x128, warp tile 64x32, BK=32 halves, NS=4
#define BM 128
#define BN 128
#define BK 32
#define NS 4
#define ROWB 64
#define TILE_A_BYTES (BM * ROWB)                   // 8192
#define TILE_B_BYTES (BN * ROWB)                   // 8192
#define STAGE_BYTES  (TILE_A_BYTES + TILE_B_BYTES) // 16384
#define GEMM_SMEM    (NS * STAGE_BYTES)            // 65536 B

// attention smem strides (halves), conflict-free ldmatrix, 16B-aligned rows
#define AT_QS 88
#define AT_VS 72

// ---------------------------------------------------------------------------
// Scratch (device globals: allocation-guard-safe)
// ---------------------------------------------------------------------------
__device__ __half g_qkvh [(size_t)S_TOT * QKV_N];  // 126 MB fp16
__device__ __half g_xh   [(size_t)S_TOT * HID];
__device__ __half g_wh   [(size_t)QKV_N * HID];
__device__ __half g_pwh  [(size_t)HID * HID];
__device__ __half g_attnh[(size_t)S_TOT * HID];

// ---------------------------------------------------------------------------
// PTX helpers (sm_100 base target)
// ---------------------------------------------------------------------------
__device__ __forceinline__ uint32_t smem_u32(const void* p) {
    uint32_t a;
    asm("{ .reg .u64 t; cvta.to.shared.u64 t, %1; cvt.u32.u64 %0, t; }"
        : "=r"(a) : "l"(p));
    return a;
}
__device__ __forceinline__ void cp16(uint32_t dst, const void* src) {
    asm volatile("cp.async.cg.shared.global [%0], [%1], 16;" :: "r"(dst), "l"(src));
}
#define CP_COMMIT()  asm volatile("cp.async.commit_group;" ::: "memory")
#define CP_WAIT(n)   asm volatile("cp.async.wait_group %0;" :: "n"(n) : "memory")

__device__ __forceinline__ void lds128(uint32_t* r, uint32_t addr) {
    asm volatile("ld.shared.v4.b32 {%0,%1,%2,%3}, [%4];"
                 : "=r"(r[0]), "=r"(r[1]), "=r"(r[2]), "=r"(r[3]) : "r"(addr));
}
__device__ __forceinline__ void ldsm4(uint32_t* r, uint32_t addr) {
    asm volatile("ldmatrix.sync.aligned.m8n8.x4.shared.b16 {%0,%1,%2,%3}, [%4];"
                 : "=r"(r[0]), "=r"(r[1]), "=r"(r[2]), "=r"(r[3]) : "r"(addr));
}
__device__ __forceinline__ void mma_f16(float* c, uint32_t a0, uint32_t a1,
                                        uint32_t a2, uint32_t a3,
                                        uint32_t b0, uint32_t b1) {
    asm volatile(
        "mma.sync.aligned.m16n8k16.row.col.f32.f16.f16.f32 "
        "{%0,%1,%2,%3}, {%4,%5,%6,%7}, {%8,%9}, {%0,%1,%2,%3};"
        : "+f"(c[0]), "+f"(c[1]), "+f"(c[2]), "+f"(c[3])
        : "r"(a0), "r"(a1), "r"(a2), "r"(a3), "r"(b0), "r"(b1));
}

// ---------------------------------------------------------------------------
// fp32 -> fp16 convert
// ---------------------------------------------------------------------------
__global__ void __launch_bounds__(256)
cvt_f16_kernel(const float4* __restrict__ src, uint2* __restrict__ dst, int n4)
{
    int i = blockIdx.x * blockDim.x + threadIdx.x;
    if (i < n4) {
        float4 v = src[i];
        __half2 h0 = __floats2half2_rn(v.x, v.y);
        __half2 h1 = __floats2half2_rn(v.z, v.w);
        uint2 o;
        o.x = *(const uint32_t*)&h0;
        o.y = *(const uint32_t*)&h1;
        dst[i] = o;
    }
}

// ---------------------------------------------------------------------------
// fp16 mma.sync GEMM: C = A*B^T + bias. Output fp16 (HALF_OUT) or fp32.
// CTA 128x128, 8 warps (2M x 4N), warp tile 64x32, 2 CTAs/SM.
// ---------------------------------------------------------------------------
__device__ __forceinline__ void load_stage(uint32_t stage_base,
                                           const __half* __restrict__ A,
                                           const __half* __restrict__ B,
                                           int bm, int bn, int K, int k0, int tid)
{
    const int row = tid >> 2;            // 0..63
    const int seg = tid & 3;
    #pragma unroll
    for (int i = 0; i < 2; i++) {
        const int r = row + i * 64;
        cp16(stage_base + r * ROWB + seg * 16,
             A + (size_t)(bm + r) * K + k0 + seg * 8);
        cp16(stage_base + TILE_A_BYTES + r * ROWB + seg * 16,
             B + (size_t)(bn + r) * K + k0 + seg * 8);
    }
}

template<bool HALF_OUT>
__global__ void __launch_bounds__(256, 2)
gemm_f16_kernel(const __half* __restrict__ A, const __half* __restrict__ B,
                const float* __restrict__ bias, void* __restrict__ Cv,
                int M, int N, int K)
{
    extern __shared__ char smraw[];
    const uint32_t smem_base = smem_u32(smraw);
    const int tid  = threadIdx.x;
    const int wid  = tid >> 5;
    const int lane = tid & 31;
    const int g    = lane >> 2;
    const int t    = lane & 3;
    const int wm   = wid >> 2;           // 0..1
    const int wn   = wid & 3;            // 0..3
    const int bm   = blockIdx.y * BM;
    const int bn   = blockIdx.x * BN;

    float acc[4][4][4];
    #pragma unroll
    for (int mi = 0; mi < 4; mi++)
        #pragma unroll
        for (int ni = 0; ni < 4; ni++)
            #pragma unroll
            for (int r = 0; r < 4; r++) acc[mi][ni][r] = 0.f;

    const int KT = K / BK;

    #pragma unroll
    for (int s = 0; s < NS - 1; s++) {
        load_stage(smem_base + s * STAGE_BYTES, A, B, bm, bn, K, s * BK, tid);
        CP_COMMIT();
    }

    const uint32_t a_base = (wm * 64 + g) * ROWB + t * 16;
    const uint32_t b_base = TILE_A_BYTES + (wn * 32 + g) * ROWB + t * 16;

    int cmp_s = 0, ld_s = NS - 1;
    for (int kt = 0; kt < KT; kt++) {
        CP_WAIT(NS - 2);
        __syncthreads();

        if (kt + NS - 1 < KT)
            load_stage(smem_base + ld_s * STAGE_BYTES, A, B, bm, bn, K,
                       (kt + NS - 1) * BK, tid);
        CP_COMMIT();
        ld_s = (ld_s + 1 == NS) ? 0 : ld_s + 1;

        const uint32_t stage = smem_base + cmp_s * STAGE_BYTES;
        cmp_s = (cmp_s + 1 == NS) ? 0 : cmp_s + 1;

        uint32_t bf[4][4];
        #pragma unroll
        for (int ni = 0; ni < 4; ni++)
            lds128(bf[ni], stage + b_base + ni * 8 * ROWB);

        #pragma unroll
        for (int mi = 0; mi < 4; mi++) {
            uint32_t ar0[4], ar1[4];
            const uint32_t ab = stage + a_base + mi * 16 * ROWB;
            lds128(ar0, ab);
            lds128(ar1, ab + 8 * ROWB);
            #pragma unroll
            for (int ni = 0; ni < 4; ni++) {
                mma_f16(acc[mi][ni], ar0[0], ar1[0], ar0[1], ar1[1],
                        bf[ni][0], bf[ni][1]);
                mma_f16(acc[mi][ni], ar0[2], ar1[2], ar0[3], ar1[3],
                        bf[ni][2], bf[ni][3]);
            }
        }
    }

    // Epilogue: bias add + store (fp16 or fp32)
    #pragma unroll
    for (int mi = 0; mi < 4; mi++) {
        const int row0 = bm + wm * 64 + mi * 16 + g;
        #pragma unroll
        for (int ni = 0; ni < 4; ni++) {
            const int col = bn + wn * 32 + ni * 8 + 2 * t;
            const float2 bb = __ldg((const float2*)&bias[col]);
            if (HALF_OUT) {
                __half* C = (__half*)Cv;
                __half2 o0 = __floats2half2_rn(acc[mi][ni][0] + bb.x,
                                               acc[mi][ni][1] + bb.y);
                __half2 o1 = __floats2half2_rn(acc[mi][ni][2] + bb.x,
                                               acc[mi][ni][3] + bb.y);
                *(__half2*)&C[(size_t)row0 * N + col]       = o0;
                *(__half2*)&C[(size_t)(row0 + 8) * N + col] = o1;
            } else {
                float* C = (float*)Cv;
                float2 o0, o1;
                o0.x = acc[mi][ni][0] + bb.x;
                o0.y = acc[mi][ni][1] + bb.y;
                o1.x = acc[mi][ni][2] + bb.x;
                o1.y = acc[mi][ni][3] + bb.y;
                *(float2*)&C[(size_t)row0 * N + col]       = o0;
                *(float2*)&C[(size_t)(row0 + 8) * N + col] = o1;
            }
        }
    }
}

// ---------------------------------------------------------------------------
// Tensor-core windowed attention with fused RoPE (fp16 qkv input).
// One CTA (128 thr, 4 warps) per (window, head).
// ---------------------------------------------------------------------------
__global__ void __launch_bounds__(128)
attn_mma_kernel(const __half* __restrict__ qkv,
                const float* __restrict__ cosT,
                const float* __restrict__ sinT,
                __half* __restrict__ outp)
{
    __shared__ __align__(16) __half smQ [WIN * AT_QS];
    __shared__ __align__(16) __half smK [WIN * AT_QS];
    __shared__ __align__(16) __half smVt[HD * AT_VS];

    const int tid = threadIdx.x;
    const int w   = blockIdx.x >> 4;
    const int h   = blockIdx.x & 15;
    const int s0  = w * WIN;
    const float scale = 0.11180339887498949f;   // 1/sqrt(80)

    // ---- load q,k with RoPE (q pre-scaled), V transposed ------------------
    for (int i = tid; i < WIN * ROT; i += 128) {
        const int r = i / ROT, j = i % ROT;
        const size_t base = (size_t)(s0 + r) * QKV_N + h * HD;
        const float c  = cosT[(s0 + r) * ROT + j];
        const float sn = sinT[(s0 + r) * ROT + j];
        const float q1 = __half2float(qkv[base + j]);
        const float q2 = __half2float(qkv[base + j + ROT]);
        smQ[r * AT_QS + j]       = __float2half_rn((q1 * c - q2 * sn) * scale);
        smQ[r * AT_QS + j + ROT] = __float2half_rn((q2 * c + q1 * sn) * scale);
        const float k1 = __half2float(qkv[base + HID + j]);
        const float k2 = __half2float(qkv[base + HID + j + ROT]);
        smK[r * AT_QS + j]       = __float2half_rn(k1 * c - k2 * sn);
        smK[r * AT_QS + j + ROT] = __float2half_rn(k2 * c + k1 * sn);
    }
    for (int i = tid; i < WIN * HD; i += 128) {
        const int r = i / HD, d = i % HD;
        smVt[d * AT_VS + r] = qkv[(size_t)(s0 + r) * QKV_N + 2 * HID + h * HD + d];
    }
    __syncthreads();

    const int wid  = tid >> 5;
    const int lane = tid & 31;
    const int g    = lane >> 2;
    const int t    = lane & 3;
    const int l8   = lane & 7;
    const int sel  = lane >> 3;

    const uint32_t qb = smem_u32(smQ);
    const uint32_t kb = smem_u32(smK);
    const uint32_t vb = smem_u32(smVt);

    const uint32_t a_row  = (uint32_t)(wid * 16 + (sel & 1) * 8 + l8);
    const uint32_t a_coff = (uint32_t)((sel >> 1) * 8);
    const uint32_t b_roff = (uint32_t)((sel >> 1) * 8 + l8);
    const uint32_t b_coff = (uint32_t)((sel & 1) * 8);

    // ---- QK^T -------------------------------------------------------------
    float c[8][4];
    #pragma unroll
    for (int j = 0; j < 8; j++)
        #pragma unroll
        for (int r = 0; r < 4; r++) c[j][r] = 0.f;

    #pragma unroll
    for (int kc = 0; kc < 5; kc++) {
        uint32_t a[4];
        ldsm4(a, qb + (a_row * AT_QS + kc * 16 + a_coff) * 2);
        #pragma unroll
        for (int np = 0; np < 4; np++) {
            uint32_t b[4];
            ldsm4(b, kb + ((np * 16 + b_roff) * AT_QS + kc * 16 + b_coff) * 2);
            mma_f16(c[2 * np],     a[0], a[1], a[2], a[3], b[0], b[1]);
            mma_f16(c[2 * np + 1], a[0], a[1], a[2], a[3], b[2], b[3]);
        }
    }

    // ---- softmax in registers ---------------------------------------------
    float m0 = -1e30f, m1 = -1e30f;
    #pragma unroll
    for (int j = 0; j < 8; j++) {
        m0 = fmaxf(m0, fmaxf(c[j][0], c[j][1]));
        m1 = fmaxf(m1, fmaxf(c[j][2], c[j][3]));
    }
    m0 = fmaxf(m0, __shfl_xor_sync(~0u, m0, 1));
    m0 = fmaxf(m0, __shfl_xor_sync(~0u, m0, 2));
    m1 = fmaxf(m1, __shfl_xor_sync(~0u, m1, 1));
    m1 = fmaxf(m1, __shfl_xor_sync(~0u, m1, 2));

    float su0 = 0.f, su1 = 0.f;
    #pragma unroll
    for (int j = 0; j < 8; j++) {
        c[j][0] = __expf(c[j][0] - m0);
        c[j][1] = __expf(c[j][1] - m0);
        c[j][2] = __expf(c[j][2] - m1);
        c[j][3] = __expf(c[j][3] - m1);
        su0 += c[j][0] + c[j][1];
        su1 += c[j][2] + c[j][3];
    }
    su0 += __shfl_xor_sync(~0u, su0, 1);
    su0 += __shfl_xor_sync(~0u, su0, 2);
    su1 += __shfl_xor_sync(~0u, su1, 1);
    su1 += __shfl_xor_sync(~0u, su1, 2);
    const float inv0 = 1.f / su0, inv1 = 1.f / su1;

    // ---- P as PV A-fragments ----------------------------------------------
    uint32_t ap[4][4];
    #pragma unroll
    for (int j2 = 0; j2 < 4; j2++) {
        __half2 h0 = __floats2half2_rn(c[2 * j2][0] * inv0,     c[2 * j2][1] * inv0);
        __half2 h1 = __floats2half2_rn(c[2 * j2][2] * inv1,     c[2 * j2][3] * inv1);
        __half2 h2 = __floats2half2_rn(c[2 * j2 + 1][0] * inv0, c[2 * j2 + 1][1] * inv0);
        __half2 h3 = __floats2half2_rn(c[2 * j2 + 1][2] * inv1, c[2 * j2 + 1][3] * inv1);
        ap[j2][0] = *(uint32_t*)&h0;
        ap[j2][1] = *(uint32_t*)&h1;
        ap[j2][2] = *(uint32_t*)&h2;
        ap[j2][3] = *(uint32_t*)&h3;
    }

    // ---- PV ---------------------------------------------------------------
    float o[10][4];
    #pragma unroll
    for (int nt = 0; nt < 10; nt++)
        #pragma unroll
        for (int r = 0; r < 4; r++) o[nt][r] = 0.f;

    #pragma unroll
    for (int j2 = 0; j2 < 4; j2++) {
        #pragma unroll
        for (int dp = 0; dp < 5; dp++) {
            uint32_t b[4];
            ldsm4(b, vb + ((dp * 16 + b_roff) * AT_VS + j2 * 16 + b_coff) * 2);
            mma_f16(o[2 * dp],     ap[j2][0], ap[j2][1], ap[j2][2], ap[j2][3],
                    b[0], b[1]);
            mma_f16(o[2 * dp + 1], ap[j2][0], ap[j2][1], ap[j2][2], ap[j2][3],
                    b[2], b[3]);
        }
    }

    // ---- store fp16 output ------------------------------------------------
    const int row0 = s0 + wid * 16 + g;
    #pragma unroll
    for (int nt = 0; nt < 10; nt++) {
        const int d = nt * 8 + 2 * t;
        __half2 lo = __floats2half2_rn(o[nt][0], o[nt][1]);
        __half2 hi = __floats2half2_rn(o[nt][2], o[nt][3]);
        *(__half2*)&outp[(size_t)row0 * HID + h * HD + d]       = lo;
        *(__half2*)&outp[(size_t)(row0 + 8) * HID + h * HD + d] = hi;
    }
}

// ---------------------------------------------------------------------------
// Launch
// ---------------------------------------------------------------------------
extern "C" void kernel_launch(void* const* d_in, const int* in_sizes, int n_in,
                              void* d_out, int out_size)
{
    const float* x      = (const float*)d_in[0];
    const float* cosT   = (const float*)d_in[1];
    const float* sinT   = (const float*)d_in[2];
    const float* qkv_w  = (const float*)d_in[3];
    const float* qkv_b  = (const float*)d_in[4];
    const float* proj_w = (const float*)d_in[5];
    const float* proj_b = (const float*)d_in[6];
    float* out = (float*)d_out;

    __half *qkvh, *xh, *wh, *pwh, *attnh;
    cudaGetSymbolAddress((void**)&qkvh,  g_qkvh);
    cudaGetSymbolAddress((void**)&xh,    g_xh);
    cudaGetSymbolAddress((void**)&wh,    g_wh);
    cudaGetSymbolAddress((void**)&pwh,   g_pwh);
    cudaGetSymbolAddress((void**)&attnh, g_attnh);

    cudaFuncSetAttribute(gemm_f16_kernel<true>,
                         cudaFuncAttributeMaxDynamicSharedMemorySize, GEMM_SMEM);
    cudaFuncSetAttribute(gemm_f16_kernel<false>,
                         cudaFuncAttributeMaxDynamicSharedMemorySize, GEMM_SMEM);

    // 0) convert inputs to fp16
    {
        int n4x = S_TOT * HID / 4;
        int n4w = QKV_N * HID / 4;
        int n4p = HID * HID / 4;
        cvt_f16_kernel<<<(n4x + 255) / 256, 256>>>((const float4*)x,     (uint2*)xh,  n4x);
        cvt_f16_kernel<<<(n4w + 255) / 256, 256>>>((const float4*)qkv_w, (uint2*)wh,  n4w);
        cvt_f16_kernel<<<(n4p + 255) / 256, 256>>>((const float4*)proj_w,(uint2*)pwh, n4p);
    }
    // 1) QKV GEMM + bias -> g_qkvh (fp16)
    {
        dim3 grid(QKV_N / BN, S_TOT / BM);   // (30, 128)
        gemm_f16_kernel<true><<<grid, 256, GEMM_SMEM>>>(xh, wh, qkv_b, qkvh,
                                                        S_TOT, QKV_N, HID);
    }
    // 2) tensor-core attention with fused RoPE -> g_attnh (fp16)
    {
        attn_mma_kernel<<<NW * NH, 128>>>(qkvh, cosT, sinT, attnh);
    }
    // 3) output projection + bias -> d_out (fp32)
    {
        dim3 grid(HID / BN, S_TOT / BM);     // (10, 128)
        gemm_f16_kernel<false><<<grid, 256, GEMM_SMEM>>>(attnh, pwh, proj_b, out,
                                                         S_TOT, HID, HID);
    }
}

// round 11
// speedup vs baseline: 7.4767x; 1.0441x over previous
#include <cuda_runtime.h>
#include <cuda_fp16.h>
#include <cstdint>

// Problem constants
#define S_TOT  16384
#define HID    1280
#define NH     16
#define HD     80
#define WIN    64
#define NW     256
#define QKV_N  3840
#define ROT    40

// fp16 mma.sync GEMM: CTA 128x128, 4 warps, warp tile 64x64, BK=32, NS=4,
// 2 CTAs/SM. Tensor-bound: smem traffic 96KB/kt/SM < tensor 1056cyc/kt/SM.
#define BM 128
#define BN 128
#define BK 32
#define NS 4
#define ROWB 64
#define TILE_A_BYTES (BM * ROWB)                   // 8192
#define TILE_B_BYTES (BN * ROWB)                   // 8192
#define STAGE_BYTES  (TILE_A_BYTES + TILE_B_BYTES) // 16384
#define GEMM_SMEM    (NS * STAGE_BYTES)            // 65536 B

// attention smem strides (halves), conflict-free ldmatrix, 16B-aligned rows
#define AT_QS 88
#define AT_VS 72

// ---------------------------------------------------------------------------
// Scratch (device globals: allocation-guard-safe)
// ---------------------------------------------------------------------------
__device__ __half g_qkvh [(size_t)S_TOT * QKV_N];  // 126 MB fp16
__device__ __half g_xh   [(size_t)S_TOT * HID];
__device__ __half g_wh   [(size_t)QKV_N * HID];
__device__ __half g_pwh  [(size_t)HID * HID];
__device__ __half g_attnh[(size_t)S_TOT * HID];

// ---------------------------------------------------------------------------
// PTX helpers (sm_100 base target)
// ---------------------------------------------------------------------------
__device__ __forceinline__ uint32_t smem_u32(const void* p) {
    uint32_t a;
    asm("{ .reg .u64 t; cvta.to.shared.u64 t, %1; cvt.u32.u64 %0, t; }"
        : "=r"(a) : "l"(p));
    return a;
}
__device__ __forceinline__ void cp16(uint32_t dst, const void* src) {
    asm volatile("cp.async.cg.shared.global [%0], [%1], 16;" :: "r"(dst), "l"(src));
}
#define CP_COMMIT()  asm volatile("cp.async.commit_group;" ::: "memory")
#define CP_WAIT(n)   asm volatile("cp.async.wait_group %0;" :: "n"(n) : "memory")

__device__ __forceinline__ void lds128(uint32_t* r, uint32_t addr) {
    asm volatile("ld.shared.v4.b32 {%0,%1,%2,%3}, [%4];"
                 : "=r"(r[0]), "=r"(r[1]), "=r"(r[2]), "=r"(r[3]) : "r"(addr));
}
__device__ __forceinline__ void ldsm4(uint32_t* r, uint32_t addr) {
    asm volatile("ldmatrix.sync.aligned.m8n8.x4.shared.b16 {%0,%1,%2,%3}, [%4];"
                 : "=r"(r[0]), "=r"(r[1]), "=r"(r[2]), "=r"(r[3]) : "r"(addr));
}
__device__ __forceinline__ void mma_f16(float* c, uint32_t a0, uint32_t a1,
                                        uint32_t a2, uint32_t a3,
                                        uint32_t b0, uint32_t b1) {
    asm volatile(
        "mma.sync.aligned.m16n8k16.row.col.f32.f16.f16.f32 "
        "{%0,%1,%2,%3}, {%4,%5,%6,%7}, {%8,%9}, {%0,%1,%2,%3};"
        : "+f"(c[0]), "+f"(c[1]), "+f"(c[2]), "+f"(c[3])
        : "r"(a0), "r"(a1), "r"(a2), "r"(a3), "r"(b0), "r"(b1));
}

// ---------------------------------------------------------------------------
// fp32 -> fp16 convert
// ---------------------------------------------------------------------------
__global__ void __launch_bounds__(256)
cvt_f16_kernel(const float4* __restrict__ src, uint2* __restrict__ dst, int n4)
{
    int i = blockIdx.x * blockDim.x + threadIdx.x;
    if (i < n4) {
        float4 v = src[i];
        __half2 h0 = __floats2half2_rn(v.x, v.y);
        __half2 h1 = __floats2half2_rn(v.z, v.w);
        uint2 o;
        o.x = *(const uint32_t*)&h0;
        o.y = *(const uint32_t*)&h1;
        dst[i] = o;
    }
}

// ---------------------------------------------------------------------------
// fp16 mma.sync GEMM: C = A*B^T + bias. Output fp16 (HALF_OUT) or fp32.
// 128 threads, 4 warps (2M x 2N), warp tile 64x64, 2 CTAs/SM.
// ---------------------------------------------------------------------------
__device__ __forceinline__ void load_stage(uint32_t stage_base,
                                           const __half* __restrict__ A,
                                           const __half* __restrict__ B,
                                           int bm, int bn, int K, int k0, int tid)
{
    const int row = tid >> 2;            // 0..31
    const int seg = tid & 3;
    #pragma unroll
    for (int i = 0; i < 4; i++) {
        const int r = row + i * 32;
        cp16(stage_base + r * ROWB + seg * 16,
             A + (size_t)(bm + r) * K + k0 + seg * 8);
        cp16(stage_base + TILE_A_BYTES + r * ROWB + seg * 16,
             B + (size_t)(bn + r) * K + k0 + seg * 8);
    }
}

template<bool HALF_OUT>
__global__ void __launch_bounds__(128, 2)
gemm_f16_kernel(const __half* __restrict__ A, const __half* __restrict__ B,
                const float* __restrict__ bias, void* __restrict__ Cv,
                int M, int N, int K)
{
    extern __shared__ char smraw[];
    const uint32_t smem_base = smem_u32(smraw);
    const int tid  = threadIdx.x;
    const int wid  = tid >> 5;
    const int lane = tid & 31;
    const int g    = lane >> 2;
    const int t    = lane & 3;
    const int wm   = wid >> 1;           // 0..1
    const int wn   = wid & 1;            // 0..1
    const int bm   = blockIdx.y * BM;
    const int bn   = blockIdx.x * BN;

    float acc[4][8][4];
    #pragma unroll
    for (int mi = 0; mi < 4; mi++)
        #pragma unroll
        for (int ni = 0; ni < 8; ni++)
            #pragma unroll
            for (int r = 0; r < 4; r++) acc[mi][ni][r] = 0.f;

    const int KT = K / BK;

    #pragma unroll
    for (int s = 0; s < NS - 1; s++) {
        load_stage(smem_base + s * STAGE_BYTES, A, B, bm, bn, K, s * BK, tid);
        CP_COMMIT();
    }

    const uint32_t a_base = (wm * 64 + g) * ROWB + t * 16;
    const uint32_t b_base = TILE_A_BYTES + (wn * 64 + g) * ROWB + t * 16;

    int cmp_s = 0, ld_s = NS - 1;
    for (int kt = 0; kt < KT; kt++) {
        CP_WAIT(NS - 2);
        __syncthreads();

        if (kt + NS - 1 < KT)
            load_stage(smem_base + ld_s * STAGE_BYTES, A, B, bm, bn, K,
                       (kt + NS - 1) * BK, tid);
        CP_COMMIT();
        ld_s = (ld_s + 1 == NS) ? 0 : ld_s + 1;

        const uint32_t stage = smem_base + cmp_s * STAGE_BYTES;
        cmp_s = (cmp_s + 1 == NS) ? 0 : cmp_s + 1;

        uint32_t bf[8][4];
        #pragma unroll
        for (int ni = 0; ni < 8; ni++)
            lds128(bf[ni], stage + b_base + ni * 8 * ROWB);

        #pragma unroll
        for (int mi = 0; mi < 4; mi++) {
            uint32_t ar0[4], ar1[4];
            const uint32_t ab = stage + a_base + mi * 16 * ROWB;
            lds128(ar0, ab);
            lds128(ar1, ab + 8 * ROWB);
            #pragma unroll
            for (int ni = 0; ni < 8; ni++) {
                mma_f16(acc[mi][ni], ar0[0], ar1[0], ar0[1], ar1[1],
                        bf[ni][0], bf[ni][1]);
                mma_f16(acc[mi][ni], ar0[2], ar1[2], ar0[3], ar1[3],
                        bf[ni][2], bf[ni][3]);
            }
        }
    }

    // Epilogue: bias add + store (fp16 or fp32)
    #pragma unroll
    for (int mi = 0; mi < 4; mi++) {
        const int row0 = bm + wm * 64 + mi * 16 + g;
        #pragma unroll
        for (int ni = 0; ni < 8; ni++) {
            const int col = bn + wn * 64 + ni * 8 + 2 * t;
            const float2 bb = __ldg((const float2*)&bias[col]);
            if (HALF_OUT) {
                __half* C = (__half*)Cv;
                __half2 o0 = __floats2half2_rn(acc[mi][ni][0] + bb.x,
                                               acc[mi][ni][1] + bb.y);
                __half2 o1 = __floats2half2_rn(acc[mi][ni][2] + bb.x,
                                               acc[mi][ni][3] + bb.y);
                *(__half2*)&C[(size_t)row0 * N + col]       = o0;
                *(__half2*)&C[(size_t)(row0 + 8) * N + col] = o1;
            } else {
                float* C = (float*)Cv;
                float2 o0, o1;
                o0.x = acc[mi][ni][0] + bb.x;
                o0.y = acc[mi][ni][1] + bb.y;
                o1.x = acc[mi][ni][2] + bb.x;
                o1.y = acc[mi][ni][3] + bb.y;
                *(float2*)&C[(size_t)row0 * N + col]       = o0;
                *(float2*)&C[(size_t)(row0 + 8) * N + col] = o1;
            }
        }
    }
}

// ---------------------------------------------------------------------------
// Tensor-core windowed attention with fused RoPE (fp16 qkv input).
// One CTA (128 thr, 4 warps) per (window, head).
// ---------------------------------------------------------------------------
__global__ void __launch_bounds__(128)
attn_mma_kernel(const __half* __restrict__ qkv,
                const float* __restrict__ cosT,
                const float* __restrict__ sinT,
                __half* __restrict__ outp)
{
    __shared__ __align__(16) __half smQ [WIN * AT_QS];
    __shared__ __align__(16) __half smK [WIN * AT_QS];
    __shared__ __align__(16) __half smVt[HD * AT_VS];

    const int tid = threadIdx.x;
    const int w   = blockIdx.x >> 4;
    const int h   = blockIdx.x & 15;
    const int s0  = w * WIN;
    const float scale = 0.11180339887498949f;   // 1/sqrt(80)

    // ---- load q,k with RoPE (q pre-scaled), V transposed ------------------
    for (int i = tid; i < WIN * ROT; i += 128) {
        const int r = i / ROT, j = i % ROT;
        const size_t base = (size_t)(s0 + r) * QKV_N + h * HD;
        const float c  = cosT[(s0 + r) * ROT + j];
        const float sn = sinT[(s0 + r) * ROT + j];
        const float q1 = __half2float(qkv[base + j]);
        const float q2 = __half2float(qkv[base + j + ROT]);
        smQ[r * AT_QS + j]       = __float2half_rn((q1 * c - q2 * sn) * scale);
        smQ[r * AT_QS + j + ROT] = __float2half_rn((q2 * c + q1 * sn) * scale);
        const float k1 = __half2float(qkv[base + HID + j]);
        const float k2 = __half2float(qkv[base + HID + j + ROT]);
        smK[r * AT_QS + j]       = __float2half_rn(k1 * c - k2 * sn);
        smK[r * AT_QS + j + ROT] = __float2half_rn(k2 * c + k1 * sn);
    }
    for (int i = tid; i < WIN * HD; i += 128) {
        const int r = i / HD, d = i % HD;
        smVt[d * AT_VS + r] = qkv[(size_t)(s0 + r) * QKV_N + 2 * HID + h * HD + d];
    }
    __syncthreads();

    const int wid  = tid >> 5;
    const int lane = tid & 31;
    const int g    = lane >> 2;
    const int t    = lane & 3;
    const int l8   = lane & 7;
    const int sel  = lane >> 3;

    const uint32_t qb = smem_u32(smQ);
    const uint32_t kb = smem_u32(smK);
    const uint32_t vb = smem_u32(smVt);

    const uint32_t a_row  = (uint32_t)(wid * 16 + (sel & 1) * 8 + l8);
    const uint32_t a_coff = (uint32_t)((sel >> 1) * 8);
    const uint32_t b_roff = (uint32_t)((sel >> 1) * 8 + l8);
    const uint32_t b_coff = (uint32_t)((sel & 1) * 8);

    // ---- QK^T -------------------------------------------------------------
    float c[8][4];
    #pragma unroll
    for (int j = 0; j < 8; j++)
        #pragma unroll
        for (int r = 0; r < 4; r++) c[j][r] = 0.f;

    #pragma unroll
    for (int kc = 0; kc < 5; kc++) {
        uint32_t a[4];
        ldsm4(a, qb + (a_row * AT_QS + kc * 16 + a_coff) * 2);
        #pragma unroll
        for (int np = 0; np < 4; np++) {
            uint32_t b[4];
            ldsm4(b, kb + ((np * 16 + b_roff) * AT_QS + kc * 16 + b_coff) * 2);
            mma_f16(c[2 * np],     a[0], a[1], a[2], a[3], b[0], b[1]);
            mma_f16(c[2 * np + 1], a[0], a[1], a[2], a[3], b[2], b[3]);
        }
    }

    // ---- softmax in registers ---------------------------------------------
    float m0 = -1e30f, m1 = -1e30f;
    #pragma unroll
    for (int j = 0; j < 8; j++) {
        m0 = fmaxf(m0, fmaxf(c[j][0], c[j][1]));
        m1 = fmaxf(m1, fmaxf(c[j][2], c[j][3]));
    }
    m0 = fmaxf(m0, __shfl_xor_sync(~0u, m0, 1));
    m0 = fmaxf(m0, __shfl_xor_sync(~0u, m0, 2));
    m1 = fmaxf(m1, __shfl_xor_sync(~0u, m1, 1));
    m1 = fmaxf(m1, __shfl_xor_sync(~0u, m1, 2));

    float su0 = 0.f, su1 = 0.f;
    #pragma unroll
    for (int j = 0; j < 8; j++) {
        c[j][0] = __expf(c[j][0] - m0);
        c[j][1] = __expf(c[j][1] - m0);
        c[j][2] = __expf(c[j][2] - m1);
        c[j][3] = __expf(c[j][3] - m1);
        su0 += c[j][0] + c[j][1];
        su1 += c[j][2] + c[j][3];
    }
    su0 += __shfl_xor_sync(~0u, su0, 1);
    su0 += __shfl_xor_sync(~0u, su0, 2);
    su1 += __shfl_xor_sync(~0u, su1, 1);
    su1 += __shfl_xor_sync(~0u, su1, 2);
    const float inv0 = 1.f / su0, inv1 = 1.f / su1;

    // ---- P as PV A-fragments ----------------------------------------------
    uint32_t ap[4][4];
    #pragma unroll
    for (int j2 = 0; j2 < 4; j2++) {
        __half2 h0 = __floats2half2_rn(c[2 * j2][0] * inv0,     c[2 * j2][1] * inv0);
        __half2 h1 = __floats2half2_rn(c[2 * j2][2] * inv1,     c[2 * j2][3] * inv1);
        __half2 h2 = __floats2half2_rn(c[2 * j2 + 1][0] * inv0, c[2 * j2 + 1][1] * inv0);
        __half2 h3 = __floats2half2_rn(c[2 * j2 + 1][2] * inv1, c[2 * j2 + 1][3] * inv1);
        ap[j2][0] = *(uint32_t*)&h0;
        ap[j2][1] = *(uint32_t*)&h1;
        ap[j2][2] = *(uint32_t*)&h2;
        ap[j2][3] = *(uint32_t*)&h3;
    }

    // ---- PV ---------------------------------------------------------------
    float o[10][4];
    #pragma unroll
    for (int nt = 0; nt < 10; nt++)
        #pragma unroll
        for (int r = 0; r < 4; r++) o[nt][r] = 0.f;

    #pragma unroll
    for (int j2 = 0; j2 < 4; j2++) {
        #pragma unroll
        for (int dp = 0; dp < 5; dp++) {
            uint32_t b[4];
            ldsm4(b, vb + ((dp * 16 + b_roff) * AT_VS + j2 * 16 + b_coff) * 2);
            mma_f16(o[2 * dp],     ap[j2][0], ap[j2][1], ap[j2][2], ap[j2][3],
                    b[0], b[1]);
            mma_f16(o[2 * dp + 1], ap[j2][0], ap[j2][1], ap[j2][2], ap[j2][3],
                    b[2], b[3]);
        }
    }

    // ---- store fp16 output ------------------------------------------------
    const int row0 = s0 + wid * 16 + g;
    #pragma unroll
    for (int nt = 0; nt < 10; nt++) {
        const int d = nt * 8 + 2 * t;
        __half2 lo = __floats2half2_rn(o[nt][0], o[nt][1]);
        __half2 hi = __floats2half2_rn(o[nt][2], o[nt][3]);
        *(__half2*)&outp[(size_t)row0 * HID + h * HD + d]       = lo;
        *(__half2*)&outp[(size_t)(row0 + 8) * HID + h * HD + d] = hi;
    }
}

// ---------------------------------------------------------------------------
// Launch
// ---------------------------------------------------------------------------
extern "C" void kernel_launch(void* const* d_in, const int* in_sizes, int n_in,
                              void* d_out, int out_size)
{
    const float* x      = (const float*)d_in[0];
    const float* cosT   = (const float*)d_in[1];
    const float* sinT   = (const float*)d_in[2];
    const float* qkv_w  = (const float*)d_in[3];
    const float* qkv_b  = (const float*)d_in[4];
    const float* proj_w = (const float*)d_in[5];
    const float* proj_b = (const float*)d_in[6];
    float* out = (float*)d_out;

    __half *qkvh, *xh, *wh, *pwh, *attnh;
    cudaGetSymbolAddress((void**)&qkvh,  g_qkvh);
    cudaGetSymbolAddress((void**)&xh,    g_xh);
    cudaGetSymbolAddress((void**)&wh,    g_wh);
    cudaGetSymbolAddress((void**)&pwh,   g_pwh);
    cudaGetSymbolAddress((void**)&attnh, g_attnh);

    cudaFuncSetAttribute(gemm_f16_kernel<true>,
                         cudaFuncAttributeMaxDynamicSharedMemorySize, GEMM_SMEM);
    cudaFuncSetAttribute(gemm_f16_kernel<false>,
                         cudaFuncAttributeMaxDynamicSharedMemorySize, GEMM_SMEM);

    // 0) convert inputs to fp16
    {
        int n4x = S_TOT * HID / 4;
        int n4w = QKV_N * HID / 4;
        int n4p = HID * HID / 4;
        cvt_f16_kernel<<<(n4x + 255) / 256, 256>>>((const float4*)x,     (uint2*)xh,  n4x);
        cvt_f16_kernel<<<(n4w + 255) / 256, 256>>>((const float4*)qkv_w, (uint2*)wh,  n4w);
        cvt_f16_kernel<<<(n4p + 255) / 256, 256>>>((const float4*)proj_w,(uint2*)pwh, n4p);
    }
    // 1) QKV GEMM + bias -> g_qkvh (fp16)
    {
        dim3 grid(QKV_N / BN, S_TOT / BM);   // (30, 128)
        gemm_f16_kernel<true><<<grid, 128, GEMM_SMEM>>>(xh, wh, qkv_b, qkvh,
                                                        S_TOT, QKV_N, HID);
    }
    // 2) tensor-core attention with fused RoPE -> g_attnh (fp16)
    {
        attn_mma_kernel<<<NW * NH, 128>>>(qkvh, cosT, sinT, attnh);
    }
    // 3) output projection + bias -> d_out (fp32)
    {
        dim3 grid(HID / BN, S_TOT / BM);     // (10, 128)
        gemm_f16_kernel<false><<<grid, 128, GEMM_SMEM>>>(attnh, pwh, proj_b, out,
                                                         S_TOT, HID, HID);
    }
}